// round 4
// baseline (speedup 1.0000x reference)
#include <cuda_runtime.h>
#include <math.h>

// Problem constants
#define T_STEPS 512
#define B_SZ    64
#define IN_SZ   1024
#define H_SZ    1024
#define G4      (4 * H_SZ)           // 4096
#define M_TOTAL (T_STEPS * B_SZ)     // 32768

// Scratch: X4 precompute [T*B, 4H] (512 MB) and double-buffered cell state.
__device__ float g_X4[(long long)M_TOTAL * G4];
__device__ float g_c[2][B_SZ * H_SZ];

// ---------------------------------------------------------------------------
// Phase 1: X4 = X @ Wx^T + b      (M=32768, N=4096, K=1024)
// A = X [M][K] row-major (K contiguous), B = Wx [N][K] row-major (K contiguous)
// 128x128 block tile, BK=16, 256 threads, 8x8 micro-tile.
// ---------------------------------------------------------------------------
__global__ __launch_bounds__(256) void gemm_x4_kernel(
    const float* __restrict__ X,
    const float* __restrict__ Wx,
    const float* __restrict__ bias)
{
    __shared__ float As[16][132];   // [k][m], padded
    __shared__ float Bs[16][132];   // [k][n], padded

    const int tid = threadIdx.x;
    const int m0  = blockIdx.y * 128;
    const int n0  = blockIdx.x * 128;
    const int tx  = tid & 15;      // 0..15 -> 8 columns each
    const int ty  = tid >> 4;      // 0..15 -> 8 rows each

    float acc[8][8];
#pragma unroll
    for (int i = 0; i < 8; i++)
#pragma unroll
        for (int j = 0; j < 8; j++) acc[i][j] = 0.0f;

    for (int kt = 0; kt < IN_SZ; kt += 16) {
        // Load A tile (128 m x 16 k) and B tile (128 n x 16 k), transposed into smem.
#pragma unroll
        for (int r = 0; r < 2; r++) {
            const int idx = tid + r * 256;       // 0..511 float4 slots
            const int mm  = idx >> 2;            // 0..127
            const int kq  = idx & 3;             // 0..3 (k = kq*4)
            const float4 av = *(const float4*)(X  + (long long)(m0 + mm) * IN_SZ + kt + kq * 4);
            As[kq * 4 + 0][mm] = av.x;
            As[kq * 4 + 1][mm] = av.y;
            As[kq * 4 + 2][mm] = av.z;
            As[kq * 4 + 3][mm] = av.w;
            const float4 bv = *(const float4*)(Wx + (long long)(n0 + mm) * IN_SZ + kt + kq * 4);
            Bs[kq * 4 + 0][mm] = bv.x;
            Bs[kq * 4 + 1][mm] = bv.y;
            Bs[kq * 4 + 2][mm] = bv.z;
            Bs[kq * 4 + 3][mm] = bv.w;
        }
        __syncthreads();

#pragma unroll
        for (int kk = 0; kk < 16; kk++) {
            float a[8], b[8];
            *(float4*)&a[0] = *(const float4*)&As[kk][ty * 8];
            *(float4*)&a[4] = *(const float4*)&As[kk][ty * 8 + 4];
            *(float4*)&b[0] = *(const float4*)&Bs[kk][tx * 8];
            *(float4*)&b[4] = *(const float4*)&Bs[kk][tx * 8 + 4];
#pragma unroll
            for (int i = 0; i < 8; i++)
#pragma unroll
                for (int j = 0; j < 8; j++)
                    acc[i][j] = fmaf(a[i], b[j], acc[i][j]);
        }
        __syncthreads();
    }

    // Epilogue: add bias, store to g_X4.
    float bv[8];
#pragma unroll
    for (int j = 0; j < 8; j++) bv[j] = bias[n0 + tx * 8 + j];

#pragma unroll
    for (int i = 0; i < 8; i++) {
        const long long row = m0 + ty * 8 + i;
        float* cp = g_X4 + row * G4 + n0 + tx * 8;
        float4 o0, o1;
        o0.x = acc[i][0] + bv[0]; o0.y = acc[i][1] + bv[1];
        o0.z = acc[i][2] + bv[2]; o0.w = acc[i][3] + bv[3];
        o1.x = acc[i][4] + bv[4]; o1.y = acc[i][5] + bv[5];
        o1.z = acc[i][6] + bv[6]; o1.w = acc[i][7] + bv[7];
        *(float4*)(cp)     = o0;
        *(float4*)(cp + 4) = o1;
    }
}

// ---------------------------------------------------------------------------
// Phase 2: one fused timestep.
// pre[b, col] = X4[t][b][col] + sum_k c_prev[b][k] * Wh[col][k]
// Block owns 8 h-indices -> 32 gate columns (8 per gate), all 64 batch rows.
// 128 blocks, 128 threads, 4x4 micro-tile, BK=32. Gates + mask fused.
// ---------------------------------------------------------------------------
__global__ __launch_bounds__(128) void lstm_step_kernel(
    const int t,
    const float* __restrict__ c0,
    const float* __restrict__ h0,
    const float* __restrict__ Wh,      // [4096][1024]
    const int*   __restrict__ mask,    // [T][B]
    float* __restrict__ hiddens)       // [T][B][H] (d_out head)
{
    __shared__ float Cs[32][68];   // [k][b]
    __shared__ float Ws[32][36];   // [k][lc]
    __shared__ float Ps[64][33];   // pre-activations [b][lc]

    const float* X4t    = g_X4 + (long long)t * B_SZ * G4;
    const float* c_prev = (t == 0) ? c0 : g_c[(t - 1) & 1];
    const float* h_prev = (t == 0) ? h0 : hiddens + (long long)(t - 1) * B_SZ * H_SZ;
    float*       c_out  = g_c[t & 1];
    float*       h_out  = hiddens + (long long)t * B_SZ * H_SZ;
    const int*   mask_t = mask + t * B_SZ;

    const int tid = threadIdx.x;
    const int h0i = blockIdx.x * 8;          // this block's h range [h0i, h0i+8)
    const int ry  = tid >> 3;                // 0..15
    const int cx  = tid & 7;                 // 0..7
    const int r0  = ry * 4;                  // batch rows r0..r0+3
    const int lc0 = cx * 4;                  // local cols lc0..lc0+3 (same gate)

    float acc[4][4];
    // Init accumulators with X4 values (includes bias from phase 1).
#pragma unroll
    for (int i = 0; i < 4; i++)
#pragma unroll
        for (int j = 0; j < 4; j++) {
            const int lc  = lc0 + j;
            const int col = (lc >> 3) * H_SZ + h0i + (lc & 7);
            acc[i][j] = X4t[(r0 + i) * G4 + col];
        }

    for (int kt = 0; kt < H_SZ; kt += 32) {
        // Load c_prev tile: 64 b x 32 k = 512 float4 slots, 4 per thread.
#pragma unroll
        for (int r = 0; r < 4; r++) {
            const int idx = tid + r * 128;
            const int bb  = idx >> 3;
            const int kq  = idx & 7;
            const float4 v = *(const float4*)(c_prev + bb * H_SZ + kt + kq * 4);
            Cs[kq * 4 + 0][bb] = v.x;
            Cs[kq * 4 + 1][bb] = v.y;
            Cs[kq * 4 + 2][bb] = v.z;
            Cs[kq * 4 + 3][bb] = v.w;
        }
        // Load Wh tile: 32 cols x 32 k = 256 float4 slots, 2 per thread.
#pragma unroll
        for (int r = 0; r < 2; r++) {
            const int idx = tid + r * 128;
            const int lc  = idx >> 3;
            const int kq  = idx & 7;
            const int col = (lc >> 3) * H_SZ + h0i + (lc & 7);
            const float4 v = *(const float4*)(Wh + (long long)col * H_SZ + kt + kq * 4);
            Ws[kq * 4 + 0][lc] = v.x;
            Ws[kq * 4 + 1][lc] = v.y;
            Ws[kq * 4 + 2][lc] = v.z;
            Ws[kq * 4 + 3][lc] = v.w;
        }
        __syncthreads();

#pragma unroll
        for (int kk = 0; kk < 32; kk++) {
            const float4 cv = *(const float4*)&Cs[kk][r0];
            const float4 wv = *(const float4*)&Ws[kk][lc0];
            const float cvv[4] = {cv.x, cv.y, cv.z, cv.w};
            const float wvv[4] = {wv.x, wv.y, wv.z, wv.w};
#pragma unroll
            for (int i = 0; i < 4; i++)
#pragma unroll
                for (int j = 0; j < 4; j++)
                    acc[i][j] = fmaf(cvv[i], wvv[j], acc[i][j]);
        }
        __syncthreads();
    }

    // Stage pre-activations so each (b, h) pair sees all 4 gates.
#pragma unroll
    for (int i = 0; i < 4; i++)
#pragma unroll
        for (int j = 0; j < 4; j++)
            Ps[r0 + i][lc0 + j] = acc[i][j];
    __syncthreads();

    // Epilogue: 64 b x 8 h = 512 pairs, 4 per thread.
#pragma unroll
    for (int q = 0; q < 4; q++) {
        const int p = tid + q * 128;
        const int b = p >> 3;
        const int j = p & 7;
        const float xi = Ps[b][j];
        const float xf = Ps[b][8 + j];
        const float xo = Ps[b][16 + j];
        const float xg = Ps[b][24 + j];

        const float ig = 1.0f / (1.0f + expf(-xi));
        const float fg = 1.0f / (1.0f + expf(-xf));
        const float og = 1.0f / (1.0f + expf(-xo));
        const float gg = tanhf(xg);

        const int hg = h0i + j;
        const float cp = c_prev[b * H_SZ + hg];
        float c = fg * cp + ig * gg;
        float h = og * tanhf(c);
        if (mask_t[b] == 0) {               // mask is exactly 0/1 -> exact blend
            h = h_prev[b * H_SZ + hg];
            c = cp;
        }
        h_out[b * H_SZ + hg] = h;
        c_out[b * H_SZ + hg] = c;
    }
}

// ---------------------------------------------------------------------------
// Tail: h_last = hiddens[T-1], c_last = final cell buffer.
// ---------------------------------------------------------------------------
__global__ void tail_kernel(const float* __restrict__ hiddens,
                            float* __restrict__ h_last,
                            float* __restrict__ c_last)
{
    const int i = blockIdx.x * blockDim.x + threadIdx.x;
    if (i < B_SZ * H_SZ) {
        h_last[i] = hiddens[(long long)(T_STEPS - 1) * B_SZ * H_SZ + i];
        c_last[i] = g_c[(T_STEPS - 1) & 1][i];
    }
}

// ---------------------------------------------------------------------------
// Launch: inputs per metadata order:
// 0: X [T,B,IN] f32   1: h0 [B,H] f32   2: c0 [B,H] f32   3: mask [T,B] i32
// 4: W_x_ifoc [4H,IN] f32   5: W_h_ifoc [4H,H] f32   6: b_ifoc [4H] f32
// d_out: [hiddens (T*B*H) | h_last (B*H) | c_last (B*H)] f32
// ---------------------------------------------------------------------------
extern "C" void kernel_launch(void* const* d_in, const int* in_sizes, int n_in,
                              void* d_out, int out_size)
{
    const float* X    = (const float*)d_in[0];
    const float* h0   = (const float*)d_in[1];
    const float* c0   = (const float*)d_in[2];
    const int*   mask = (const int*)d_in[3];
    const float* Wx   = (const float*)d_in[4];
    const float* Wh   = (const float*)d_in[5];
    const float* bias = (const float*)d_in[6];

    float* out     = (float*)d_out;
    float* hiddens = out;                                     // T*B*H
    float* h_last  = out + (long long)T_STEPS * B_SZ * H_SZ;  // B*H
    float* c_last  = h_last + B_SZ * H_SZ;                    // B*H

    // Phase 1: input projection for all timesteps.
    dim3 g1(G4 / 128, M_TOTAL / 128);   // (32, 256)
    gemm_x4_kernel<<<g1, 256>>>(X, Wx, bias);

    // Phase 2: 512 dependent fused steps.
    for (int t = 0; t < T_STEPS; t++)
        lstm_step_kernel<<<H_SZ / 8, 128>>>(t, c0, h0, Wh, mask, hiddens);

    // Tail: final carries.
    tail_kernel<<<(B_SZ * H_SZ + 255) / 256, 256>>>(hiddens, h_last, c_last);
}

// round 9
// speedup vs baseline: 1.3559x; 1.3559x over previous
#include <cuda_runtime.h>
#include <cuda_bf16.h>
#include <math.h>
#include <stdint.h>

// Problem constants
#define T_STEPS 512
#define B_SZ    64
#define IN_SZ   1024
#define H_SZ    1024
#define G4      4096
#define M_TOTAL 32768          // T*B
#define NBLK    128            // persistent blocks (<=148 SMs -> all co-resident)

// ---------------------------------------------------------------------------
// Device scratch (no allocs allowed)
// ---------------------------------------------------------------------------
__device__ __align__(256) float         g_X4[(long long)M_TOTAL * G4];    // 512 MB
__device__ __align__(256) __nv_bfloat16 g_Xh[(long long)M_TOTAL * IN_SZ]; // 64 MB
__device__ __align__(256) __nv_bfloat16 g_Xl[(long long)M_TOTAL * IN_SZ]; // 64 MB
__device__ __align__(256) __nv_bfloat16 g_Wxh[(long long)G4 * IN_SZ];     // 8 MB
__device__ __align__(256) __nv_bfloat16 g_Wxl[(long long)G4 * IN_SZ];     // 8 MB
__device__ __align__(256) float         g_c3[3][B_SZ * H_SZ];             // cell ring
__device__ int g_bar;

// ---------------------------------------------------------------------------
// Helpers (plain sm_103-safe PTX only: ldmatrix / mma.sync / cp.async)
// ---------------------------------------------------------------------------
__device__ __forceinline__ uint32_t smem_u32(const void* p) {
    uint32_t a;
    asm("{ .reg .u64 t; cvta.to.shared.u64 t, %1; cvt.u32.u64 %0, t; }" : "=r"(a) : "l"(p));
    return a;
}

__device__ __forceinline__ void cp16(uint32_t s, const void* g) {
    asm volatile("cp.async.cg.shared.global [%0], [%1], 16;" :: "r"(s), "l"(g));
}
#define CP_COMMIT() asm volatile("cp.async.commit_group;" ::: "memory")
#define CP_WAIT(n)  asm volatile("cp.async.wait_group %0;" :: "n"(n) : "memory")

__device__ __forceinline__ void ldsm_x4(uint32_t& r0, uint32_t& r1, uint32_t& r2,
                                        uint32_t& r3, uint32_t addr) {
    asm volatile("ldmatrix.sync.aligned.m8n8.x4.shared.b16 {%0,%1,%2,%3}, [%4];"
                 : "=r"(r0), "=r"(r1), "=r"(r2), "=r"(r3) : "r"(addr));
}

__device__ __forceinline__ void mma_bf16(float* c, const uint32_t* a, const uint32_t* b) {
    asm volatile(
        "mma.sync.aligned.m16n8k16.row.col.f32.bf16.bf16.f32 "
        "{%0,%1,%2,%3}, {%4,%5,%6,%7}, {%8,%9}, {%0,%1,%2,%3};"
        : "+f"(c[0]), "+f"(c[1]), "+f"(c[2]), "+f"(c[3])
        : "r"(a[0]), "r"(a[1]), "r"(a[2]), "r"(a[3]), "r"(b[0]), "r"(b[1]));
}

// ---------------------------------------------------------------------------
// bf16 hi/lo split kernels (write __device__ symbols directly; no symbol-addr
// lookups in the capture path)
// ---------------------------------------------------------------------------
__global__ void split_X_kernel(const float* __restrict__ src) {
    int i = blockIdx.x * blockDim.x + threadIdx.x;
    if (i < M_TOTAL * IN_SZ) {
        float x = src[i];
        __nv_bfloat16 h = __float2bfloat16(x);
        g_Xh[i] = h;
        g_Xl[i] = __float2bfloat16(x - __bfloat162float(h));
    }
}
__global__ void split_W_kernel(const float* __restrict__ src) {
    int i = blockIdx.x * blockDim.x + threadIdx.x;
    if (i < G4 * IN_SZ) {
        float x = src[i];
        __nv_bfloat16 h = __float2bfloat16(x);
        g_Wxh[i] = h;
        g_Wxl[i] = __float2bfloat16(x - __bfloat162float(h));
    }
}

// ---------------------------------------------------------------------------
// Phase 1: X4 = X @ Wx^T + b via mma.sync bf16x3 (hi*hi + hi*lo + lo*hi).
// 128(M) x 128(N) CTA tile, BK=32, 256 threads = 8 warps (4M x 2N),
// warp tile 32x64, cp.async double-buffered smem, padded rows (40 bf16).
// ---------------------------------------------------------------------------
#define SPAD        40                     // smem row stride in bf16 (80 B)
#define TILE_ELEMS  (128 * SPAD)           // bf16 per tile array
#define TILE_BYTES  (TILE_ELEMS * 2)
#define STAGE_BYTES (4 * TILE_BYTES)       // Ah, Al, Bh, Bl
#define PH1_SMEM    (2 * STAGE_BYTES)      // 81920 B

__device__ __forceinline__ void ph1_load_stage(
    uint32_t sbase, const __nv_bfloat16* Ah, const __nv_bfloat16* Al,
    const __nv_bfloat16* Bh, const __nv_bfloat16* Bl, int kt, int tid)
{
#pragma unroll
    for (int r = 0; r < 2; r++) {
        const int idx = tid + r * 256;     // 0..511 16B chunks per array
        const int row = idx >> 2;          // 0..127
        const int kq  = idx & 3;           // k0 = kq*8
        const uint32_t soff = (uint32_t)(row * SPAD + kq * 8) * 2;
        const long long goff = (long long)row * IN_SZ + kt + kq * 8;
        cp16(sbase + soff,                  Ah + goff);
        cp16(sbase + TILE_BYTES + soff,     Al + goff);
        cp16(sbase + 2 * TILE_BYTES + soff, Bh + goff);
        cp16(sbase + 3 * TILE_BYTES + soff, Bl + goff);
    }
}

__global__ __launch_bounds__(256, 1) void gemm_x4_mma(const float* __restrict__ bias) {
    extern __shared__ __align__(16) char smem[];
    const uint32_t sb = smem_u32(smem);

    const int tid  = threadIdx.x;
    const int wid  = tid >> 5;
    const int lane = tid & 31;
    const int n0 = blockIdx.x * 128;
    const int m0 = blockIdx.y * 128;

    const int wm = wid >> 1;               // 0..3 -> m offset
    const int wn = wid & 1;                // 0..1 -> n offset
    const int m_w = wm * 32;
    const int n_w = wn * 64;

    // ldmatrix per-lane row/k pattern
    const int lrow = lane & 15;            // 0..15
    const int lk   = (lane >> 4) * 8;      // 0 or 8

    const __nv_bfloat16* Ah = g_Xh  + (long long)m0 * IN_SZ;
    const __nv_bfloat16* Al = g_Xl  + (long long)m0 * IN_SZ;
    const __nv_bfloat16* Bh = g_Wxh + (long long)n0 * IN_SZ;
    const __nv_bfloat16* Bl = g_Wxl + (long long)n0 * IN_SZ;

    float acc[2][8][4];
#pragma unroll
    for (int i = 0; i < 2; i++)
#pragma unroll
        for (int j = 0; j < 8; j++)
#pragma unroll
            for (int q = 0; q < 4; q++) acc[i][j][q] = 0.0f;

    ph1_load_stage(sb, Ah, Al, Bh, Bl, 0, tid);
    CP_COMMIT();

    for (int kt = 0; kt < 32; kt++) {
        if (kt + 1 < 32) {
            ph1_load_stage(sb + ((kt + 1) & 1) * STAGE_BYTES, Ah, Al, Bh, Bl,
                           (kt + 1) * 32, tid);
            CP_COMMIT();
            CP_WAIT(1);
        } else {
            CP_WAIT(0);
        }
        __syncthreads();

        const uint32_t st = sb + (kt & 1) * STAGE_BYTES;
#pragma unroll
        for (int ks = 0; ks < 32; ks += 16) {
            // A fragments: 2 m-tiles, hi and lo
            uint32_t ah[2][4], al[2][4];
#pragma unroll
            for (int tm = 0; tm < 2; tm++) {
                const uint32_t ao = (uint32_t)((m_w + tm * 16 + lrow) * SPAD + ks + lk) * 2;
                ldsm_x4(ah[tm][0], ah[tm][1], ah[tm][2], ah[tm][3], st + ao);
                ldsm_x4(al[tm][0], al[tm][1], al[tm][2], al[tm][3], st + TILE_BYTES + ao);
            }
            // B fragments: 8 n-tiles (4 x ldmatrix covering 16 n each), hi and lo
            uint32_t bh[8][2], bl[8][2];
#pragma unroll
            for (int tn2 = 0; tn2 < 4; tn2++) {
                const uint32_t bo = (uint32_t)((n_w + tn2 * 16 + lrow) * SPAD + ks + lk) * 2;
                ldsm_x4(bh[tn2 * 2][0], bh[tn2 * 2 + 1][0], bh[tn2 * 2][1], bh[tn2 * 2 + 1][1],
                        st + 2 * TILE_BYTES + bo);
                ldsm_x4(bl[tn2 * 2][0], bl[tn2 * 2 + 1][0], bl[tn2 * 2][1], bl[tn2 * 2 + 1][1],
                        st + 3 * TILE_BYTES + bo);
            }
#pragma unroll
            for (int tm = 0; tm < 2; tm++)
#pragma unroll
                for (int tn = 0; tn < 8; tn++) {
                    mma_bf16(acc[tm][tn], ah[tm], bh[tn]);   // hi*hi
                    mma_bf16(acc[tm][tn], ah[tm], bl[tn]);   // hi*lo
                    mma_bf16(acc[tm][tn], al[tm], bh[tn]);   // lo*hi
                }
        }
        __syncthreads();
    }

    // Epilogue: fragment layout -> (row, col) pairs; add bias; store fp32.
    const int gr = lane >> 2;              // 0..7
    const int gc = (lane & 3) * 2;         // 0,2,4,6
#pragma unroll
    for (int tm = 0; tm < 2; tm++) {
        const int row = m0 + m_w + tm * 16 + gr;
#pragma unroll
        for (int tn = 0; tn < 8; tn++) {
            const int col = n0 + n_w + tn * 8 + gc;
            const float2 bv = *(const float2*)(bias + col);
            float2 o0, o1;
            o0.x = acc[tm][tn][0] + bv.x; o0.y = acc[tm][tn][1] + bv.y;
            o1.x = acc[tm][tn][2] + bv.x; o1.y = acc[tm][tn][3] + bv.y;
            *(float2*)(g_X4 + (long long)row * G4 + col)       = o0;
            *(float2*)(g_X4 + (long long)(row + 8) * G4 + col) = o1;
        }
    }
}

// ---------------------------------------------------------------------------
// Phase 2: persistent LSTM. 128 blocks x 256 threads, all 512 steps.
// Block owns 8 h-indices (32 gate cols). Wh slice (32 cols x 1024 k, 128 KB)
// resident in smem. Warps 0-3: k in [0,512); warps 4-7: k in [512,1024).
// Grid barrier per step via monotonic atomic counter (all blocks co-resident:
// 165 KB smem -> 1 block/SM, 128 blocks <= 148 SMs).
// ---------------------------------------------------------------------------
#define PH2_SMEM_FLOATS (32768 + 2 * 32 * 68 + 2 * 64 * 33)

__global__ void reset_bar_kernel() { g_bar = 0; }

__global__ __launch_bounds__(256) void lstm_persistent(
    const float* __restrict__ c0, const float* __restrict__ h0,
    const float* __restrict__ Whr,     // [4096][1024]
    const int*   __restrict__ mask,    // [T][B]
    float* __restrict__ hiddens,       // [T][B][H]
    float* __restrict__ h_last, float* __restrict__ c_last)
{
    extern __shared__ __align__(16) float sm2[];
    float* Ws  = sm2;                       // [1024][32]
    float* Cs  = sm2 + 32768;               // [2][32][68]
    float* Ps1 = Cs + 2 * 32 * 68;          // [64][33]
    float* Ps0 = Ps1 + 64 * 33;             // [64][33]

    const int tid = threadIdx.x;
    const int h0i = blockIdx.x * 8;
    const int g2  = tid >> 7;               // k-half group
    const int tt  = tid & 127;
    const int r0  = (tt >> 3) * 4;          // batch rows
    const int lc0 = (tt & 7) * 4;           // local gate-cols
    const int kbase = g2 * 512;
    float* Csg = Cs + g2 * (32 * 68);

    // Preload this block's Wh slice: Ws[k][lc], col = gate*H + h0i + (lc&7)
    for (int idx = tid; idx < 32 * 256; idx += 256) {
        const int lc = idx & 31;
        const int kq = idx >> 5;            // k = kq*4
        const int col = (lc >> 3) * H_SZ + h0i + (lc & 7);
        const float4 v = *(const float4*)(Whr + (long long)col * H_SZ + kq * 4);
        Ws[(kq * 4 + 0) * 32 + lc] = v.x;
        Ws[(kq * 4 + 1) * 32 + lc] = v.y;
        Ws[(kq * 4 + 2) * 32 + lc] = v.z;
        Ws[(kq * 4 + 3) * 32 + lc] = v.w;
    }
    __syncthreads();

    for (int t = 0; t < T_STEPS; t++) {
        const float* c_prev = (t == 0) ? c0 : g_c3[(t - 1) % 3];
        float*       c_out  = g_c3[t % 3];
        const float* X4t    = g_X4 + (long long)t * B_SZ * G4;

        float acc[4][4];
#pragma unroll
        for (int i = 0; i < 4; i++)
#pragma unroll
            for (int j = 0; j < 4; j++) acc[i][j] = 0.0f;

        // prefetch kt=0 c tile
        float4 pc[4];
#pragma unroll
        for (int r = 0; r < 4; r++) {
            const int idx = tt + r * 128;
            const int bb = idx >> 3, kq = idx & 7;
            pc[r] = __ldcg((const float4*)(c_prev + bb * H_SZ + kbase + kq * 4));
        }

        for (int kt = 0; kt < 16; kt++) {
            __syncthreads();                // Cs free (prev compute done)
#pragma unroll
            for (int r = 0; r < 4; r++) {
                const int idx = tt + r * 128;
                const int bb = idx >> 3, kq = idx & 7;
                const float4 v = pc[r];
                Csg[(kq * 4 + 0) * 68 + bb] = v.x;
                Csg[(kq * 4 + 1) * 68 + bb] = v.y;
                Csg[(kq * 4 + 2) * 68 + bb] = v.z;
                Csg[(kq * 4 + 3) * 68 + bb] = v.w;
            }
            if (kt < 15) {
#pragma unroll
                for (int r = 0; r < 4; r++) {
                    const int idx = tt + r * 128;
                    const int bb = idx >> 3, kq = idx & 7;
                    pc[r] = __ldcg((const float4*)(c_prev + bb * H_SZ + kbase + (kt + 1) * 32 + kq * 4));
                }
            }
            __syncthreads();                // Cs ready
            const float* wrow = Ws + (kbase + kt * 32) * 32;
#pragma unroll
            for (int kk = 0; kk < 32; kk++) {
                const float4 cv = *(const float4*)&Csg[kk * 68 + r0];
                const float4 wv = *(const float4*)&wrow[kk * 32 + lc0];
                const float cva[4] = {cv.x, cv.y, cv.z, cv.w};
                const float wva[4] = {wv.x, wv.y, wv.z, wv.w};
#pragma unroll
                for (int i = 0; i < 4; i++)
#pragma unroll
                    for (int j = 0; j < 4; j++)
                        acc[i][j] = fmaf(cva[i], wva[j], acc[i][j]);
            }
        }

        // Combine k-halves + X4, stage pre-activations.
        if (g2 == 1) {
#pragma unroll
            for (int i = 0; i < 4; i++)
#pragma unroll
                for (int j = 0; j < 4; j++)
                    Ps1[(r0 + i) * 33 + lc0 + j] = acc[i][j];
        }
        __syncthreads();
        if (g2 == 0) {
            const int gate = lc0 >> 3;
            const int cbase = gate * H_SZ + h0i + (lc0 & 7);
#pragma unroll
            for (int i = 0; i < 4; i++) {
                const float4 xv = __ldcs((const float4*)(X4t + (long long)(r0 + i) * G4 + cbase));
                const float xa[4] = {xv.x, xv.y, xv.z, xv.w};
#pragma unroll
                for (int j = 0; j < 4; j++)
                    Ps0[(r0 + i) * 33 + lc0 + j] =
                        acc[i][j] + Ps1[(r0 + i) * 33 + lc0 + j] + xa[j];
            }
        }
        __syncthreads();

        // Epilogue: 64 b x 8 h = 512 pairs, 2 per thread.
#pragma unroll
        for (int q = 0; q < 2; q++) {
            const int p = tid + q * 256;
            const int b = p >> 3, j = p & 7;
            const int hg = h0i + j;
            const float xi = Ps0[b * 33 + j];
            const float xf = Ps0[b * 33 + 8 + j];
            const float xo = Ps0[b * 33 + 16 + j];
            const float xg = Ps0[b * 33 + 24 + j];

            const float ig = 1.0f / (1.0f + expf(-xi));
            const float fg = 1.0f / (1.0f + expf(-xf));
            const float og = 1.0f / (1.0f + expf(-xo));

            const float cp = __ldcg(c_prev + b * H_SZ + hg);
            float c = fg * cp + ig * tanhf(xg);
            float h = og * tanhf(c);
            if (mask[t * B_SZ + b] == 0) {
                h = (t == 0) ? h0[b * H_SZ + hg]
                             : __ldcg(hiddens + (long long)(t - 1) * B_SZ * H_SZ + b * H_SZ + hg);
                c = cp;
            }
            hiddens[(long long)t * B_SZ * H_SZ + b * H_SZ + hg] = h;
            c_out[b * H_SZ + hg] = c;
            if (t == T_STEPS - 1) {
                h_last[b * H_SZ + hg] = h;
                c_last[b * H_SZ + hg] = c;
            }
        }

        // Grid barrier (all 128 blocks resident by construction).
        __threadfence();
        __syncthreads();
        if (tid == 0) {
            atomicAdd(&g_bar, 1);
            const int target = NBLK * (t + 1);
            while (*(volatile int*)&g_bar < target) { }
        }
        __syncthreads();
        __threadfence();
    }
}

// ---------------------------------------------------------------------------
// Launch. Inputs (metadata order):
// 0: X [T,B,IN] f32  1: h0 [B,H] f32  2: c0 [B,H] f32  3: mask [T,B] i32
// 4: W_x_ifoc [4H,IN] f32  5: W_h_ifoc [4H,H] f32  6: b_ifoc [4H] f32
// d_out: [hiddens (T*B*H) | h_last (B*H) | c_last (B*H)] f32
// ---------------------------------------------------------------------------
extern "C" void kernel_launch(void* const* d_in, const int* in_sizes, int n_in,
                              void* d_out, int out_size)
{
    const float* X    = (const float*)d_in[0];
    const float* h0   = (const float*)d_in[1];
    const float* c0   = (const float*)d_in[2];
    const int*   mask = (const int*)d_in[3];
    const float* Wx   = (const float*)d_in[4];
    const float* Whr  = (const float*)d_in[5];
    const float* bias = (const float*)d_in[6];

    float* out     = (float*)d_out;
    float* hiddens = out;
    float* h_last  = out + (long long)T_STEPS * B_SZ * H_SZ;
    float* c_last  = h_last + B_SZ * H_SZ;

    cudaFuncSetAttribute(gemm_x4_mma, cudaFuncAttributeMaxDynamicSharedMemorySize, PH1_SMEM);
    cudaFuncSetAttribute(lstm_persistent, cudaFuncAttributeMaxDynamicSharedMemorySize,
                         PH2_SMEM_FLOATS * (int)sizeof(float));

    // bf16 hi/lo splits
    split_X_kernel<<<(M_TOTAL * IN_SZ + 255) / 256, 256>>>(X);
    split_W_kernel<<<(G4 * IN_SZ + 255) / 256, 256>>>(Wx);

    // Phase 1: HMMA input projection (bf16x3 -> fp32).
    {
        dim3 g(G4 / 128, M_TOTAL / 128);    // (32, 256)
        gemm_x4_mma<<<g, 256, PH1_SMEM>>>(bias);
    }

    // Phase 2: persistent recurrence.
    reset_bar_kernel<<<1, 1>>>();
    lstm_persistent<<<NBLK, 256, PH2_SMEM_FLOATS * (int)sizeof(float)>>>(
        c0, h0, Whr, mask, hiddens, h_last, c_last);
}

// round 10
// speedup vs baseline: 2.6125x; 1.9267x over previous
#include <cuda_runtime.h>
#include <cuda_bf16.h>
#include <math.h>
#include <stdint.h>

// Problem constants
#define T_STEPS 512
#define B_SZ    64
#define IN_SZ   1024
#define H_SZ    1024
#define G4      4096
#define M_TOTAL 32768          // T*B
#define NBLK    128            // persistent blocks (<=148 SMs -> all co-resident)

// ---------------------------------------------------------------------------
// Device scratch (no allocs allowed)
// ---------------------------------------------------------------------------
__device__ __align__(256) float         g_X4[(long long)M_TOTAL * G4];    // 512 MB
__device__ __align__(256) __nv_bfloat16 g_Xh[(long long)M_TOTAL * IN_SZ]; // 64 MB
__device__ __align__(256) __nv_bfloat16 g_Xl[(long long)M_TOTAL * IN_SZ]; // 64 MB
__device__ __align__(256) __nv_bfloat16 g_Wxh[(long long)G4 * IN_SZ];     // 8 MB
__device__ __align__(256) __nv_bfloat16 g_Wxl[(long long)G4 * IN_SZ];     // 8 MB
__device__ __align__(256) float         g_c2[2][B_SZ * H_SZ];             // fp32 cell ring
__device__ __align__(256) __nv_bfloat16 g_ch[2][B_SZ * H_SZ];             // cell hi ring
__device__ __align__(256) __nv_bfloat16 g_cl[2][B_SZ * H_SZ];             // cell lo ring
__device__ int g_bar;

// ---------------------------------------------------------------------------
// Helpers (plain sm_103-safe PTX only: ldmatrix / mma.sync / cp.async)
// ---------------------------------------------------------------------------
__device__ __forceinline__ uint32_t smem_u32(const void* p) {
    uint32_t a;
    asm("{ .reg .u64 t; cvta.to.shared.u64 t, %1; cvt.u32.u64 %0, t; }" : "=r"(a) : "l"(p));
    return a;
}

__device__ __forceinline__ void cp16(uint32_t s, const void* g) {
    asm volatile("cp.async.cg.shared.global [%0], [%1], 16;" :: "r"(s), "l"(g));
}
#define CP_COMMIT() asm volatile("cp.async.commit_group;" ::: "memory")
#define CP_WAIT(n)  asm volatile("cp.async.wait_group %0;" :: "n"(n) : "memory")

__device__ __forceinline__ void ldsm_x4(uint32_t& r0, uint32_t& r1, uint32_t& r2,
                                        uint32_t& r3, uint32_t addr) {
    asm volatile("ldmatrix.sync.aligned.m8n8.x4.shared.b16 {%0,%1,%2,%3}, [%4];"
                 : "=r"(r0), "=r"(r1), "=r"(r2), "=r"(r3) : "r"(addr));
}

__device__ __forceinline__ void mma_bf16(float* c, const uint32_t* a, const uint32_t* b) {
    asm volatile(
        "mma.sync.aligned.m16n8k16.row.col.f32.bf16.bf16.f32 "
        "{%0,%1,%2,%3}, {%4,%5,%6,%7}, {%8,%9}, {%0,%1,%2,%3};"
        : "+f"(c[0]), "+f"(c[1]), "+f"(c[2]), "+f"(c[3])
        : "r"(a[0]), "r"(a[1]), "r"(a[2]), "r"(a[3]), "r"(b[0]), "r"(b[1]));
}

// ---------------------------------------------------------------------------
// bf16 hi/lo split kernels
// ---------------------------------------------------------------------------
__global__ void split_X_kernel(const float* __restrict__ src) {
    int i = blockIdx.x * blockDim.x + threadIdx.x;
    if (i < M_TOTAL * IN_SZ) {
        float x = src[i];
        __nv_bfloat16 h = __float2bfloat16(x);
        g_Xh[i] = h;
        g_Xl[i] = __float2bfloat16(x - __bfloat162float(h));
    }
}
__global__ void split_W_kernel(const float* __restrict__ src) {
    int i = blockIdx.x * blockDim.x + threadIdx.x;
    if (i < G4 * IN_SZ) {
        float x = src[i];
        __nv_bfloat16 h = __float2bfloat16(x);
        g_Wxh[i] = h;
        g_Wxl[i] = __float2bfloat16(x - __bfloat162float(h));
    }
}
// Seed cell ring slot 1 with c0 (fp32 + hi/lo split). Step t reads slot (t+1)&1.
__global__ void init_c_kernel(const float* __restrict__ c0) {
    int i = blockIdx.x * blockDim.x + threadIdx.x;
    if (i < B_SZ * H_SZ) {
        float x = c0[i];
        __nv_bfloat16 h = __float2bfloat16(x);
        g_c2[1][i] = x;
        g_ch[1][i] = h;
        g_cl[1][i] = __float2bfloat16(x - __bfloat162float(h));
    }
}

// ---------------------------------------------------------------------------
// Phase 1: X4 = X @ Wx^T + b via mma.sync bf16x3 (UNCHANGED from R9 — passing).
// ---------------------------------------------------------------------------
#define SPAD        40
#define TILE_ELEMS  (128 * SPAD)
#define TILE_BYTES  (TILE_ELEMS * 2)
#define STAGE_BYTES (4 * TILE_BYTES)
#define PH1_SMEM    (2 * STAGE_BYTES)

__device__ __forceinline__ void ph1_load_stage(
    uint32_t sbase, const __nv_bfloat16* Ah, const __nv_bfloat16* Al,
    const __nv_bfloat16* Bh, const __nv_bfloat16* Bl, int kt, int tid)
{
#pragma unroll
    for (int r = 0; r < 2; r++) {
        const int idx = tid + r * 256;
        const int row = idx >> 2;
        const int kq  = idx & 3;
        const uint32_t soff = (uint32_t)(row * SPAD + kq * 8) * 2;
        const long long goff = (long long)row * IN_SZ + kt + kq * 8;
        cp16(sbase + soff,                  Ah + goff);
        cp16(sbase + TILE_BYTES + soff,     Al + goff);
        cp16(sbase + 2 * TILE_BYTES + soff, Bh + goff);
        cp16(sbase + 3 * TILE_BYTES + soff, Bl + goff);
    }
}

__global__ __launch_bounds__(256, 1) void gemm_x4_mma(const float* __restrict__ bias) {
    extern __shared__ __align__(16) char smem[];
    const uint32_t sb = smem_u32(smem);

    const int tid  = threadIdx.x;
    const int wid  = tid >> 5;
    const int lane = tid & 31;
    const int n0 = blockIdx.x * 128;
    const int m0 = blockIdx.y * 128;

    const int wm = wid >> 1;
    const int wn = wid & 1;
    const int m_w = wm * 32;
    const int n_w = wn * 64;

    const int lrow = lane & 15;
    const int lk   = (lane >> 4) * 8;

    const __nv_bfloat16* Ah = g_Xh  + (long long)m0 * IN_SZ;
    const __nv_bfloat16* Al = g_Xl  + (long long)m0 * IN_SZ;
    const __nv_bfloat16* Bh = g_Wxh + (long long)n0 * IN_SZ;
    const __nv_bfloat16* Bl = g_Wxl + (long long)n0 * IN_SZ;

    float acc[2][8][4];
#pragma unroll
    for (int i = 0; i < 2; i++)
#pragma unroll
        for (int j = 0; j < 8; j++)
#pragma unroll
            for (int q = 0; q < 4; q++) acc[i][j][q] = 0.0f;

    ph1_load_stage(sb, Ah, Al, Bh, Bl, 0, tid);
    CP_COMMIT();

    for (int kt = 0; kt < 32; kt++) {
        if (kt + 1 < 32) {
            ph1_load_stage(sb + ((kt + 1) & 1) * STAGE_BYTES, Ah, Al, Bh, Bl,
                           (kt + 1) * 32, tid);
            CP_COMMIT();
            CP_WAIT(1);
        } else {
            CP_WAIT(0);
        }
        __syncthreads();

        const uint32_t st = sb + (kt & 1) * STAGE_BYTES;
#pragma unroll
        for (int ks = 0; ks < 32; ks += 16) {
            uint32_t ah[2][4], al[2][4];
#pragma unroll
            for (int tm = 0; tm < 2; tm++) {
                const uint32_t ao = (uint32_t)((m_w + tm * 16 + lrow) * SPAD + ks + lk) * 2;
                ldsm_x4(ah[tm][0], ah[tm][1], ah[tm][2], ah[tm][3], st + ao);
                ldsm_x4(al[tm][0], al[tm][1], al[tm][2], al[tm][3], st + TILE_BYTES + ao);
            }
            uint32_t bh[8][2], bl[8][2];
#pragma unroll
            for (int tn2 = 0; tn2 < 4; tn2++) {
                const uint32_t bo = (uint32_t)((n_w + tn2 * 16 + lrow) * SPAD + ks + lk) * 2;
                ldsm_x4(bh[tn2 * 2][0], bh[tn2 * 2 + 1][0], bh[tn2 * 2][1], bh[tn2 * 2 + 1][1],
                        st + 2 * TILE_BYTES + bo);
                ldsm_x4(bl[tn2 * 2][0], bl[tn2 * 2 + 1][0], bl[tn2 * 2][1], bl[tn2 * 2 + 1][1],
                        st + 3 * TILE_BYTES + bo);
            }
#pragma unroll
            for (int tm = 0; tm < 2; tm++)
#pragma unroll
                for (int tn = 0; tn < 8; tn++) {
                    mma_bf16(acc[tm][tn], ah[tm], bh[tn]);
                    mma_bf16(acc[tm][tn], ah[tm], bl[tn]);
                    mma_bf16(acc[tm][tn], al[tm], bh[tn]);
                }
        }
        __syncthreads();
    }

    const int gr = lane >> 2;
    const int gc = (lane & 3) * 2;
#pragma unroll
    for (int tm = 0; tm < 2; tm++) {
        const int row = m0 + m_w + tm * 16 + gr;
#pragma unroll
        for (int tn = 0; tn < 8; tn++) {
            const int col = n0 + n_w + tn * 8 + gc;
            const float2 bv = *(const float2*)(bias + col);
            float2 o0, o1;
            o0.x = acc[tm][tn][0] + bv.x; o0.y = acc[tm][tn][1] + bv.y;
            o1.x = acc[tm][tn][2] + bv.x; o1.y = acc[tm][tn][3] + bv.y;
            *(float2*)(g_X4 + (long long)row * G4 + col)       = o0;
            *(float2*)(g_X4 + (long long)(row + 8) * G4 + col) = o1;
        }
    }
}

// ---------------------------------------------------------------------------
// Phase 2: persistent tensor-core LSTM. 128 blocks x 256 threads, 512 steps.
// Block owns 8 h-indices -> 32 gate cols. pre = X4 + c_prev @ WhSlice^T via
// bf16x3 mma.sync. Wh slice resident in smem as bf16 hi/lo ([32][1032] pad).
// c staged per 64-k chunk (both k-halves, hi+lo) via cp.async double buffer
// ([64][72] pad). Warps: wid>>2 = k-half, wid&3 = 16-row m-tile.
//
// smem layout (bytes):
//   A stage : 0      .. 73728   buf*36864 + hiLo*18432 + half*9216 + row*144 + k*2
//   Ws hi   : 73728  .. 139776  col*2064 + k*2
//   Ws lo   : 139776 .. 205824
//   Ps1     : 205824 (64*33 f32)   Ps0: 214272   total 222720 <= 232448 max
// ---------------------------------------------------------------------------
#define SA_BUF    36864
#define SA_HL     18432
#define SA_HALF   9216
#define SA_ROW    144
#define SW_OFF    73728
#define SW_HL     66048
#define SW_ROW    2064
#define SPS1_OFF  205824
#define SPS0_OFF  214272
#define PH2_SMEM  222720

__global__ void reset_bar_kernel() { g_bar = 0; }

__device__ __forceinline__ void stage_c(uint32_t abase,
                                        const __nv_bfloat16* ch,
                                        const __nv_bfloat16* cl,
                                        int kc, int tid) {
    // chunk kc: k in [half*512 + kc*64, +64), hi & lo: 2048 cp16, 8/thread
#pragma unroll
    for (int r = 0; r < 8; r++) {
        const int idx  = tid + r * 256;
        const int sel  = idx >> 9;           // 0..3
        const int hl   = sel >> 1;
        const int half = sel & 1;
        const int rem  = idx & 511;
        const int row  = rem >> 3;
        const int seg  = rem & 7;
        const __nv_bfloat16* src = (hl ? cl : ch)
            + row * H_SZ + half * 512 + kc * 64 + seg * 8;
        cp16(abase + hl * SA_HL + half * SA_HALF + row * SA_ROW + seg * 16, src);
    }
}

__global__ __launch_bounds__(256, 1) void lstm_persistent(
    const float* __restrict__ h0,
    const float* __restrict__ Whr,     // [4096][1024]
    const int*   __restrict__ mask,    // [T][B]
    float* __restrict__ hiddens,       // [T][B][H]
    float* __restrict__ h_last, float* __restrict__ c_last)
{
    extern __shared__ __align__(16) char sm2[];
    const uint32_t sb = smem_u32(sm2);
    float* Ps1 = (float*)(sm2 + SPS1_OFF);
    float* Ps0 = (float*)(sm2 + SPS0_OFF);

    const int tid  = threadIdx.x;
    const int wid  = tid >> 5;
    const int lane = tid & 31;
    const int h0i  = blockIdx.x * 8;

    const int half   = wid >> 2;           // k-half
    const int m_base = (wid & 3) * 16;     // 16-row m-tile
    const int lrow = lane & 15;
    const int lk   = (lane >> 4) * 8;
    const int gr = lane >> 2;
    const int gc = (lane & 3) * 2;

    // Preload Wh slice as bf16 hi/lo: smem col lc -> Whr col (lc>>3)*H + h0i + (lc&7)
    for (int idx = tid; idx < 32 * 1024; idx += 256) {
        const int lc = idx >> 10;
        const int k  = idx & 1023;
        const int col = (lc >> 3) * H_SZ + h0i + (lc & 7);
        const float w = Whr[(long long)col * H_SZ + k];
        const __nv_bfloat16 wh = __float2bfloat16(w);
        *(__nv_bfloat16*)(sm2 + SW_OFF + lc * SW_ROW + k * 2) = wh;
        *(__nv_bfloat16*)(sm2 + SW_OFF + SW_HL + lc * SW_ROW + k * 2) =
            __float2bfloat16(w - __bfloat162float(wh));
    }
    __syncthreads();

    for (int t = 0; t < T_STEPS; t++) {
        const int si = (t + 1) & 1;                 // in slot
        const int so = t & 1;                       // out slot
        const __nv_bfloat16* chp = g_ch[si];
        const __nv_bfloat16* clp = g_cl[si];
        const float* c_prev = g_c2[si];
        const float* X4t    = g_X4 + (long long)t * B_SZ * G4;

        float acc[4][4];
#pragma unroll
        for (int i = 0; i < 4; i++)
#pragma unroll
            for (int j = 0; j < 4; j++) acc[i][j] = 0.0f;

        stage_c(sb, chp, clp, 0, tid);
        CP_COMMIT();

        for (int kc = 0; kc < 8; kc++) {
            if (kc + 1 < 8) {
                stage_c(sb + ((kc + 1) & 1) * SA_BUF, chp, clp, kc + 1, tid);
                CP_COMMIT();
                CP_WAIT(1);
            } else {
                CP_WAIT(0);
            }
            __syncthreads();

            const uint32_t ab = sb + (kc & 1) * SA_BUF + half * SA_HALF;
            const int wk0 = half * 512 + kc * 64;
#pragma unroll
            for (int ks = 0; ks < 64; ks += 16) {
                uint32_t ah[4], al[4];
                const uint32_t ao = ab + (uint32_t)(m_base + lrow) * SA_ROW + (ks + lk) * 2;
                ldsm_x4(ah[0], ah[1], ah[2], ah[3], ao);
                ldsm_x4(al[0], al[1], al[2], al[3], ao + SA_HL);

                uint32_t bh[4][2], bl[4][2];
#pragma unroll
                for (int tn2 = 0; tn2 < 2; tn2++) {
                    const uint32_t bo = sb + SW_OFF
                        + (uint32_t)(tn2 * 16 + lrow) * SW_ROW + (wk0 + ks + lk) * 2;
                    ldsm_x4(bh[tn2 * 2][0], bh[tn2 * 2 + 1][0],
                            bh[tn2 * 2][1], bh[tn2 * 2 + 1][1], bo);
                    ldsm_x4(bl[tn2 * 2][0], bl[tn2 * 2 + 1][0],
                            bl[tn2 * 2][1], bl[tn2 * 2 + 1][1], bo + SW_HL);
                }
#pragma unroll
                for (int tn = 0; tn < 4; tn++) {
                    mma_bf16(acc[tn], ah, bh[tn]);   // hi*hi
                    mma_bf16(acc[tn], ah, bl[tn]);   // hi*lo
                    mma_bf16(acc[tn], al, bh[tn]);   // lo*hi
                }
            }
            __syncthreads();
        }

        // Cross-k-half reduce + X4 add.
        if (half == 1) {
#pragma unroll
            for (int tn = 0; tn < 4; tn++) {
                const int lc = tn * 8 + gc;
                Ps1[(m_base + gr) * 33 + lc]     = acc[tn][0];
                Ps1[(m_base + gr) * 33 + lc + 1] = acc[tn][1];
                Ps1[(m_base + gr + 8) * 33 + lc]     = acc[tn][2];
                Ps1[(m_base + gr + 8) * 33 + lc + 1] = acc[tn][3];
            }
        }
        __syncthreads();
        if (half == 0) {
#pragma unroll
            for (int tn = 0; tn < 4; tn++) {
                const int lc = tn * 8 + gc;
                const int b0 = m_base + gr;
                const long long xb = (long long)tn * H_SZ + h0i + gc;
                const float2 x0 = __ldcs((const float2*)(X4t + (long long)b0 * G4 + xb));
                const float2 x1 = __ldcs((const float2*)(X4t + (long long)(b0 + 8) * G4 + xb));
                Ps0[b0 * 33 + lc]     = acc[tn][0] + Ps1[b0 * 33 + lc]     + x0.x;
                Ps0[b0 * 33 + lc + 1] = acc[tn][1] + Ps1[b0 * 33 + lc + 1] + x0.y;
                Ps0[(b0 + 8) * 33 + lc]     = acc[tn][2] + Ps1[(b0 + 8) * 33 + lc]     + x1.x;
                Ps0[(b0 + 8) * 33 + lc + 1] = acc[tn][3] + Ps1[(b0 + 8) * 33 + lc + 1] + x1.y;
            }
        }
        __syncthreads();

        // Gate epilogue: 64 b x 8 h = 512 pairs, 2 per thread.
#pragma unroll
        for (int q = 0; q < 2; q++) {
            const int p = tid + q * 256;
            const int b = p >> 3, j = p & 7;
            const int hg = h0i + j;
            const float xi = Ps0[b * 33 + j];
            const float xf = Ps0[b * 33 + 8 + j];
            const float xo = Ps0[b * 33 + 16 + j];
            const float xg = Ps0[b * 33 + 24 + j];

            const float ig = 1.0f / (1.0f + expf(-xi));
            const float fg = 1.0f / (1.0f + expf(-xf));
            const float og = 1.0f / (1.0f + expf(-xo));

            const float cp = __ldcg(c_prev + b * H_SZ + hg);
            float c = fg * cp + ig * tanhf(xg);
            float h = og * tanhf(c);
            if (mask[t * B_SZ + b] == 0) {
                h = (t == 0) ? h0[b * H_SZ + hg]
                             : __ldcg(hiddens + (long long)(t - 1) * B_SZ * H_SZ + b * H_SZ + hg);
                c = cp;
            }
            hiddens[(long long)t * B_SZ * H_SZ + b * H_SZ + hg] = h;
            g_c2[so][b * H_SZ + hg] = c;
            const __nv_bfloat16 chv = __float2bfloat16(c);
            g_ch[so][b * H_SZ + hg] = chv;
            g_cl[so][b * H_SZ + hg] = __float2bfloat16(c - __bfloat162float(chv));
            if (t == T_STEPS - 1) {
                h_last[b * H_SZ + hg] = h;
                c_last[b * H_SZ + hg] = c;
            }
        }

        // Grid barrier (all 128 blocks resident by construction).
        if (t < T_STEPS - 1) {
            __threadfence();
            __syncthreads();
            if (tid == 0) {
                atomicAdd(&g_bar, 1);
                const int target = NBLK * (t + 1);
                while (*(volatile int*)&g_bar < target) { }
            }
            __syncthreads();
        }
    }
}

// ---------------------------------------------------------------------------
// Launch. Inputs (metadata order):
// 0: X [T,B,IN] f32  1: h0 [B,H] f32  2: c0 [B,H] f32  3: mask [T,B] i32
// 4: W_x_ifoc [4H,IN] f32  5: W_h_ifoc [4H,H] f32  6: b_ifoc [4H] f32
// d_out: [hiddens (T*B*H) | h_last (B*H) | c_last (B*H)] f32
// ---------------------------------------------------------------------------
extern "C" void kernel_launch(void* const* d_in, const int* in_sizes, int n_in,
                              void* d_out, int out_size)
{
    const float* X    = (const float*)d_in[0];
    const float* h0   = (const float*)d_in[1];
    const float* c0   = (const float*)d_in[2];
    const int*   mask = (const int*)d_in[3];
    const float* Wx   = (const float*)d_in[4];
    const float* Whr  = (const float*)d_in[5];
    const float* bias = (const float*)d_in[6];

    float* out     = (float*)d_out;
    float* hiddens = out;
    float* h_last  = out + (long long)T_STEPS * B_SZ * H_SZ;
    float* c_last  = h_last + B_SZ * H_SZ;

    cudaFuncSetAttribute(gemm_x4_mma, cudaFuncAttributeMaxDynamicSharedMemorySize, PH1_SMEM);
    cudaFuncSetAttribute(lstm_persistent, cudaFuncAttributeMaxDynamicSharedMemorySize, PH2_SMEM);

    // bf16 hi/lo splits + cell ring seed
    split_X_kernel<<<(M_TOTAL * IN_SZ + 255) / 256, 256>>>(X);
    split_W_kernel<<<(G4 * IN_SZ + 255) / 256, 256>>>(Wx);
    init_c_kernel<<<(B_SZ * H_SZ + 255) / 256, 256>>>(c0);

    // Phase 1: HMMA input projection (bf16x3 -> fp32).
    {
        dim3 g(G4 / 128, M_TOTAL / 128);    // (32, 256)
        gemm_x4_mma<<<g, 256, PH1_SMEM>>>(bias);
    }

    // Phase 2: persistent tensor-core recurrence.
    reset_bar_kernel<<<1, 1>>>();
    lstm_persistent<<<NBLK, 256, PH2_SMEM>>>(h0, Whr, mask, hiddens, h_last, c_last);
}

// round 11
// speedup vs baseline: 2.8245x; 1.0812x over previous
#include <cuda_runtime.h>
#include <cuda_bf16.h>
#include <math.h>
#include <stdint.h>

// Problem constants
#define T_STEPS 512
#define B_SZ    64
#define IN_SZ   1024
#define H_SZ    1024
#define G4      4096
#define M_TOTAL 32768          // T*B
#define NBLK    128            // persistent blocks (<=148 SMs -> all co-resident)

// ---------------------------------------------------------------------------
// Device scratch (no allocs allowed)
// ---------------------------------------------------------------------------
__device__ __align__(256) float         g_X4[(long long)M_TOTAL * G4];    // 512 MB
__device__ __align__(256) __nv_bfloat16 g_Xh[(long long)M_TOTAL * IN_SZ]; // 64 MB
__device__ __align__(256) __nv_bfloat16 g_Xl[(long long)M_TOTAL * IN_SZ]; // 64 MB
__device__ __align__(256) __nv_bfloat16 g_Wxh[(long long)G4 * IN_SZ];     // 8 MB
__device__ __align__(256) __nv_bfloat16 g_Wxl[(long long)G4 * IN_SZ];     // 8 MB
__device__ __align__(256) float         g_c2[2][B_SZ * H_SZ];             // fp32 cell ring
__device__ __align__(256) __nv_bfloat16 g_ch[2][B_SZ * H_SZ];             // cell hi ring
__device__ __align__(256) __nv_bfloat16 g_cl[2][B_SZ * H_SZ];             // cell lo ring
__device__ int g_bar;

// ---------------------------------------------------------------------------
// Helpers (plain sm_103-safe PTX only: ldmatrix / mma.sync / cp.async)
// ---------------------------------------------------------------------------
__device__ __forceinline__ uint32_t smem_u32(const void* p) {
    uint32_t a;
    asm("{ .reg .u64 t; cvta.to.shared.u64 t, %1; cvt.u32.u64 %0, t; }" : "=r"(a) : "l"(p));
    return a;
}

__device__ __forceinline__ void cp16(uint32_t s, const void* g) {
    asm volatile("cp.async.cg.shared.global [%0], [%1], 16;" :: "r"(s), "l"(g));
}
#define CP_COMMIT() asm volatile("cp.async.commit_group;" ::: "memory")
#define CP_WAIT(n)  asm volatile("cp.async.wait_group %0;" :: "n"(n) : "memory")

__device__ __forceinline__ void ldsm_x4(uint32_t& r0, uint32_t& r1, uint32_t& r2,
                                        uint32_t& r3, uint32_t addr) {
    asm volatile("ldmatrix.sync.aligned.m8n8.x4.shared.b16 {%0,%1,%2,%3}, [%4];"
                 : "=r"(r0), "=r"(r1), "=r"(r2), "=r"(r3) : "r"(addr));
}

__device__ __forceinline__ void mma_bf16(float* c, const uint32_t* a, const uint32_t* b) {
    asm volatile(
        "mma.sync.aligned.m16n8k16.row.col.f32.bf16.bf16.f32 "
        "{%0,%1,%2,%3}, {%4,%5,%6,%7}, {%8,%9}, {%0,%1,%2,%3};"
        : "+f"(c[0]), "+f"(c[1]), "+f"(c[2]), "+f"(c[3])
        : "r"(a[0]), "r"(a[1]), "r"(a[2]), "r"(a[3]), "r"(b[0]), "r"(b[1]));
}

// ---------------------------------------------------------------------------
// bf16 hi/lo split kernels
// ---------------------------------------------------------------------------
__global__ void split_X_kernel(const float* __restrict__ src) {
    int i = blockIdx.x * blockDim.x + threadIdx.x;
    if (i < M_TOTAL * IN_SZ) {
        float x = src[i];
        __nv_bfloat16 h = __float2bfloat16(x);
        g_Xh[i] = h;
        g_Xl[i] = __float2bfloat16(x - __bfloat162float(h));
    }
}
__global__ void split_W_kernel(const float* __restrict__ src) {
    int i = blockIdx.x * blockDim.x + threadIdx.x;
    if (i < G4 * IN_SZ) {
        float x = src[i];
        __nv_bfloat16 h = __float2bfloat16(x);
        g_Wxh[i] = h;
        g_Wxl[i] = __float2bfloat16(x - __bfloat162float(h));
    }
}
// Seed cell ring slot 1 with c0 (fp32 + hi/lo split). Step t reads slot (t+1)&1.
__global__ void init_c_kernel(const float* __restrict__ c0) {
    int i = blockIdx.x * blockDim.x + threadIdx.x;
    if (i < B_SZ * H_SZ) {
        float x = c0[i];
        __nv_bfloat16 h = __float2bfloat16(x);
        g_c2[1][i] = x;
        g_ch[1][i] = h;
        g_cl[1][i] = __float2bfloat16(x - __bfloat162float(h));
    }
}

// ---------------------------------------------------------------------------
// Phase 1: X4 = X @ Wx^T + b via mma.sync bf16x3 (term-outer MMA ordering).
// ---------------------------------------------------------------------------
#define SPAD        40
#define TILE_ELEMS  (128 * SPAD)
#define TILE_BYTES  (TILE_ELEMS * 2)
#define STAGE_BYTES (4 * TILE_BYTES)
#define PH1_SMEM    (2 * STAGE_BYTES)

__device__ __forceinline__ void ph1_load_stage(
    uint32_t sbase, const __nv_bfloat16* Ah, const __nv_bfloat16* Al,
    const __nv_bfloat16* Bh, const __nv_bfloat16* Bl, int kt, int tid)
{
#pragma unroll
    for (int r = 0; r < 2; r++) {
        const int idx = tid + r * 256;
        const int row = idx >> 2;
        const int kq  = idx & 3;
        const uint32_t soff = (uint32_t)(row * SPAD + kq * 8) * 2;
        const long long goff = (long long)row * IN_SZ + kt + kq * 8;
        cp16(sbase + soff,                  Ah + goff);
        cp16(sbase + TILE_BYTES + soff,     Al + goff);
        cp16(sbase + 2 * TILE_BYTES + soff, Bh + goff);
        cp16(sbase + 3 * TILE_BYTES + soff, Bl + goff);
    }
}

__global__ __launch_bounds__(256, 1) void gemm_x4_mma(const float* __restrict__ bias) {
    extern __shared__ __align__(16) char smem[];
    const uint32_t sb = smem_u32(smem);

    const int tid  = threadIdx.x;
    const int wid  = tid >> 5;
    const int lane = tid & 31;
    const int n0 = blockIdx.x * 128;
    const int m0 = blockIdx.y * 128;

    const int wm = wid >> 1;
    const int wn = wid & 1;
    const int m_w = wm * 32;
    const int n_w = wn * 64;

    const int lrow = lane & 15;
    const int lk   = (lane >> 4) * 8;

    const __nv_bfloat16* Ah = g_Xh  + (long long)m0 * IN_SZ;
    const __nv_bfloat16* Al = g_Xl  + (long long)m0 * IN_SZ;
    const __nv_bfloat16* Bh = g_Wxh + (long long)n0 * IN_SZ;
    const __nv_bfloat16* Bl = g_Wxl + (long long)n0 * IN_SZ;

    float acc[2][8][4];
#pragma unroll
    for (int i = 0; i < 2; i++)
#pragma unroll
        for (int j = 0; j < 8; j++)
#pragma unroll
            for (int q = 0; q < 4; q++) acc[i][j][q] = 0.0f;

    ph1_load_stage(sb, Ah, Al, Bh, Bl, 0, tid);
    CP_COMMIT();

    for (int kt = 0; kt < 32; kt++) {
        if (kt + 1 < 32) {
            ph1_load_stage(sb + ((kt + 1) & 1) * STAGE_BYTES, Ah, Al, Bh, Bl,
                           (kt + 1) * 32, tid);
            CP_COMMIT();
            CP_WAIT(1);
        } else {
            CP_WAIT(0);
        }
        __syncthreads();

        const uint32_t st = sb + (kt & 1) * STAGE_BYTES;
#pragma unroll
        for (int ks = 0; ks < 32; ks += 16) {
            uint32_t ah[2][4], al[2][4];
#pragma unroll
            for (int tm = 0; tm < 2; tm++) {
                const uint32_t ao = (uint32_t)((m_w + tm * 16 + lrow) * SPAD + ks + lk) * 2;
                ldsm_x4(ah[tm][0], ah[tm][1], ah[tm][2], ah[tm][3], st + ao);
                ldsm_x4(al[tm][0], al[tm][1], al[tm][2], al[tm][3], st + TILE_BYTES + ao);
            }
            uint32_t bh[8][2], bl[8][2];
#pragma unroll
            for (int tn2 = 0; tn2 < 4; tn2++) {
                const uint32_t bo = (uint32_t)((n_w + tn2 * 16 + lrow) * SPAD + ks + lk) * 2;
                ldsm_x4(bh[tn2 * 2][0], bh[tn2 * 2 + 1][0], bh[tn2 * 2][1], bh[tn2 * 2 + 1][1],
                        st + 2 * TILE_BYTES + bo);
                ldsm_x4(bl[tn2 * 2][0], bl[tn2 * 2 + 1][0], bl[tn2 * 2][1], bl[tn2 * 2 + 1][1],
                        st + 3 * TILE_BYTES + bo);
            }
            // Term-outer ordering: 16 independent MMAs between accumulator reuse.
#pragma unroll
            for (int tm = 0; tm < 2; tm++)
#pragma unroll
                for (int tn = 0; tn < 8; tn++)
                    mma_bf16(acc[tm][tn], ah[tm], bh[tn]);
#pragma unroll
            for (int tm = 0; tm < 2; tm++)
#pragma unroll
                for (int tn = 0; tn < 8; tn++)
                    mma_bf16(acc[tm][tn], ah[tm], bl[tn]);
#pragma unroll
            for (int tm = 0; tm < 2; tm++)
#pragma unroll
                for (int tn = 0; tn < 8; tn++)
                    mma_bf16(acc[tm][tn], al[tm], bh[tn]);
        }
        __syncthreads();
    }

    const int gr = lane >> 2;
    const int gc = (lane & 3) * 2;
#pragma unroll
    for (int tm = 0; tm < 2; tm++) {
        const int row = m0 + m_w + tm * 16 + gr;
#pragma unroll
        for (int tn = 0; tn < 8; tn++) {
            const int col = n0 + n_w + tn * 8 + gc;
            const float2 bv = *(const float2*)(bias + col);
            float2 o0, o1;
            o0.x = acc[tm][tn][0] + bv.x; o0.y = acc[tm][tn][1] + bv.y;
            o1.x = acc[tm][tn][2] + bv.x; o1.y = acc[tm][tn][3] + bv.y;
            *(float2*)(g_X4 + (long long)row * G4 + col)       = o0;
            *(float2*)(g_X4 + (long long)(row + 8) * G4 + col) = o1;
        }
    }
}

// ---------------------------------------------------------------------------
// Phase 2: persistent tensor-core LSTM. 128 blocks x 512 threads, 512 steps.
// 16 warps = 4 k-quarters (256 k each) x 4 m-tiles (16 rows). Block owns 8
// h-indices -> 32 gate cols. Wh slice resident in smem as bf16 hi/lo.
// c staged per chunk (32 k per quarter = 128 k total, hi+lo) via cp.async
// double buffer. X4 + mask prefetched into smem overlapping the grid barrier.
// 4 k-quarter partials reduced once through smem scratch (reused A buffers).
//
// smem layout (bytes):
//   A stage : 0      .. 69632   buf*34816 + hiLo*17408 + row*272 + kseg*16
//   (P partials overlay A after last chunk: part*9216 + row*144 + col*4)
//   Ws hi   : 69632  .. 135680  col*2064 + k*2
//   Ws lo   : 135680 .. 201728
//   X4s     : 201728 .. 210944  row*144 + col*4   ([64][36] f32)
//   mask    : 210944 .. 211200
//   total 211200 <= 232448 max
// ---------------------------------------------------------------------------
#define SA_ROWB   272
#define SA_HL     17408
#define SA_BUF    34816
#define SW_OFF    69632
#define SW_HL     66048
#define SW_ROW    2064
#define SX4_OFF   201728
#define SMASK_OFF 210944
#define SP_ARR    9216
#define PH2_SMEM  211200

__global__ void reset_bar_kernel() { g_bar = 0; }

__device__ __forceinline__ void stage_c(uint32_t abase,
                                        const __nv_bfloat16* ch,
                                        const __nv_bfloat16* cl,
                                        int kc, int tid) {
    // chunk kc: per quarter q, k in [q*256 + kc*32, +32). 2048 cp16, 4/thread.
#pragma unroll
    for (int r = 0; r < 4; r++) {
        const int idx = tid + r * 512;
        const int hl  = idx >> 10;           // 0..1
        const int rem = idx & 1023;
        const int row = rem >> 4;            // 0..63
        const int seg = rem & 15;            // 16B segment (8 bf16)
        const int q   = seg >> 2;            // k-quarter
        const int kin = (seg & 3) * 8;       // k within quarter chunk
        const __nv_bfloat16* src = (hl ? cl : ch)
            + row * H_SZ + q * 256 + kc * 32 + kin;
        cp16(abase + hl * SA_HL + row * SA_ROWB + seg * 16, src);
    }
}

__global__ __launch_bounds__(512, 1) void lstm_persistent(
    const float* __restrict__ h0,
    const float* __restrict__ Whr,     // [4096][1024]
    const int*   __restrict__ mask,    // [T][B]
    float* __restrict__ hiddens,       // [T][B][H]
    float* __restrict__ h_last, float* __restrict__ c_last)
{
    extern __shared__ __align__(16) char sm2[];
    const uint32_t sb = smem_u32(sm2);

    const int tid  = threadIdx.x;
    const int wid  = tid >> 5;
    const int lane = tid & 31;
    const int h0i  = blockIdx.x * 8;

    const int q      = wid >> 2;           // k-quarter
    const int m_base = (wid & 3) * 16;     // 16-row m-tile
    const int lrow = lane & 15;
    const int lk   = (lane >> 4) * 8;
    const int gr = lane >> 2;
    const int gc = (lane & 3) * 2;

    // Preload Wh slice as bf16 hi/lo: smem col lc -> Whr col (lc>>3)*H + h0i + (lc&7)
    for (int idx = tid; idx < 32 * 1024; idx += 512) {
        const int lc = idx >> 10;
        const int k  = idx & 1023;
        const int col = (lc >> 3) * H_SZ + h0i + (lc & 7);
        const float w = Whr[(long long)col * H_SZ + k];
        const __nv_bfloat16 wh = __float2bfloat16(w);
        *(__nv_bfloat16*)(sm2 + SW_OFF + lc * SW_ROW + k * 2) = wh;
        *(__nv_bfloat16*)(sm2 + SW_OFF + SW_HL + lc * SW_ROW + k * 2) =
            __float2bfloat16(w - __bfloat162float(wh));
    }
    __syncthreads();

    for (int t = 0; t < T_STEPS; t++) {
        const int si = (t + 1) & 1;                 // in slot
        const int so = t & 1;                       // out slot
        const __nv_bfloat16* chp = g_ch[si];
        const __nv_bfloat16* clp = g_cl[si];
        const float* c_prev = g_c2[si];
        const float* X4t    = g_X4 + (long long)t * B_SZ * G4;

        // Arrive (I finished step t-1; ordering: fence+sync at end of prev iter).
        if (t > 0 && tid == 0) atomicAdd(&g_bar, 1);

        // Prefetch X4 tile + mask into smem — independent of the barrier.
        {
            const int b = tid >> 3, seg = tid & 7;
            const int gate = seg >> 1, c4 = (seg & 1) * 4;
            cp16(sb + SX4_OFF + b * 144 + seg * 16,
                 X4t + (long long)b * G4 + gate * H_SZ + h0i + c4);
            if (tid < 16) cp16(sb + SMASK_OFF + tid * 16, mask + t * B_SZ + tid * 4);
        }
        CP_COMMIT();

        // Wait for all producers of the new c slot.
        if (t > 0) {
            if (tid == 0) {
                const int target = NBLK * t;
                while (*(volatile int*)&g_bar < target) { }
            }
            __syncthreads();
        }

        float acc[4][4];
#pragma unroll
        for (int i = 0; i < 4; i++)
#pragma unroll
            for (int j = 0; j < 4; j++) acc[i][j] = 0.0f;

        stage_c(sb, chp, clp, 0, tid);
        CP_COMMIT();

        for (int kc = 0; kc < 8; kc++) {
            if (kc + 1 < 8) {
                stage_c(sb + ((kc + 1) & 1) * SA_BUF, chp, clp, kc + 1, tid);
                CP_COMMIT();
                CP_WAIT(1);
            } else {
                CP_WAIT(0);
            }
            __syncthreads();

            const uint32_t ab = sb + (kc & 1) * SA_BUF;
            const int wk0 = q * 256 + kc * 32;
#pragma unroll
            for (int ks = 0; ks < 32; ks += 16) {
                uint32_t ah[4], al[4];
                const uint32_t ao = ab + (uint32_t)(m_base + lrow) * SA_ROWB
                                  + (q * 32 + ks + lk) * 2;
                ldsm_x4(ah[0], ah[1], ah[2], ah[3], ao);
                ldsm_x4(al[0], al[1], al[2], al[3], ao + SA_HL);

                uint32_t bh[4][2], bl[4][2];
#pragma unroll
                for (int tn2 = 0; tn2 < 2; tn2++) {
                    const uint32_t bo = sb + SW_OFF
                        + (uint32_t)(tn2 * 16 + lrow) * SW_ROW + (wk0 + ks + lk) * 2;
                    ldsm_x4(bh[tn2 * 2][0], bh[tn2 * 2 + 1][0],
                            bh[tn2 * 2][1], bh[tn2 * 2 + 1][1], bo);
                    ldsm_x4(bl[tn2 * 2][0], bl[tn2 * 2 + 1][0],
                            bl[tn2 * 2][1], bl[tn2 * 2 + 1][1], bo + SW_HL);
                }
                // Term-outer: 4 independent MMAs between accumulator reuse.
#pragma unroll
                for (int tn = 0; tn < 4; tn++) mma_bf16(acc[tn], ah, bh[tn]);
#pragma unroll
                for (int tn = 0; tn < 4; tn++) mma_bf16(acc[tn], ah, bl[tn]);
#pragma unroll
                for (int tn = 0; tn < 4; tn++) mma_bf16(acc[tn], al, bh[tn]);
            }
            __syncthreads();
        }

        // Write per-quarter partials into scratch overlaying the A buffers
        // (safe: the trailing sync above guarantees all ldsm reads are done).
        {
            float* P = (float*)(sm2 + q * SP_ARR);
#pragma unroll
            for (int tn = 0; tn < 4; tn++) {
                const int lc = tn * 8 + gc;
                P[(m_base + gr) * 36 + lc]     = acc[tn][0];
                P[(m_base + gr) * 36 + lc + 1] = acc[tn][1];
                P[(m_base + gr + 8) * 36 + lc]     = acc[tn][2];
                P[(m_base + gr + 8) * 36 + lc + 1] = acc[tn][3];
            }
        }
        __syncthreads();

        // Epilogue: 512 threads, one (b, h) pair each. X4/mask from smem.
        {
            const int b = tid >> 3, j = tid & 7;
            const int hg = h0i + j;
            const float* X4s = (const float*)(sm2 + SX4_OFF);

            float pre[4];
#pragma unroll
            for (int g = 0; g < 4; g++) {
                const int col = g * 8 + j;
                float v = X4s[b * 36 + col];
#pragma unroll
                for (int qq = 0; qq < 4; qq++)
                    v += ((const float*)(sm2 + qq * SP_ARR))[b * 36 + col];
                pre[g] = v;
            }

            const float ig = 1.0f / (1.0f + expf(-pre[0]));
            const float fg = 1.0f / (1.0f + expf(-pre[1]));
            const float og = 1.0f / (1.0f + expf(-pre[2]));

            const float cp = __ldcg(c_prev + b * H_SZ + hg);
            float c = fg * cp + ig * tanhf(pre[3]);
            float h = og * tanhf(c);
            if (((const int*)(sm2 + SMASK_OFF))[b] == 0) {
                h = (t == 0) ? h0[b * H_SZ + hg]
                             : __ldcg(hiddens + (long long)(t - 1) * B_SZ * H_SZ + b * H_SZ + hg);
                c = cp;
            }
            hiddens[(long long)t * B_SZ * H_SZ + b * H_SZ + hg] = h;
            g_c2[so][b * H_SZ + hg] = c;
            const __nv_bfloat16 chv = __float2bfloat16(c);
            g_ch[so][b * H_SZ + hg] = chv;
            g_cl[so][b * H_SZ + hg] = __float2bfloat16(c - __bfloat162float(chv));
            if (t == T_STEPS - 1) {
                h_last[b * H_SZ + hg] = h;
                c_last[b * H_SZ + hg] = c;
            }
        }

        // Order c writes before the next step's arrive.
        if (t < T_STEPS - 1) {
            __threadfence();
            __syncthreads();
        }
    }
}

// ---------------------------------------------------------------------------
// Launch. Inputs (metadata order):
// 0: X [T,B,IN] f32  1: h0 [B,H] f32  2: c0 [B,H] f32  3: mask [T,B] i32
// 4: W_x_ifoc [4H,IN] f32  5: W_h_ifoc [4H,H] f32  6: b_ifoc [4H] f32
// d_out: [hiddens (T*B*H) | h_last (B*H) | c_last (B*H)] f32
// ---------------------------------------------------------------------------
extern "C" void kernel_launch(void* const* d_in, const int* in_sizes, int n_in,
                              void* d_out, int out_size)
{
    const float* X    = (const float*)d_in[0];
    const float* h0   = (const float*)d_in[1];
    const float* c0   = (const float*)d_in[2];
    const int*   mask = (const int*)d_in[3];
    const float* Wx   = (const float*)d_in[4];
    const float* Whr  = (const float*)d_in[5];
    const float* bias = (const float*)d_in[6];

    float* out     = (float*)d_out;
    float* hiddens = out;
    float* h_last  = out + (long long)T_STEPS * B_SZ * H_SZ;
    float* c_last  = h_last + B_SZ * H_SZ;

    cudaFuncSetAttribute(gemm_x4_mma, cudaFuncAttributeMaxDynamicSharedMemorySize, PH1_SMEM);
    cudaFuncSetAttribute(lstm_persistent, cudaFuncAttributeMaxDynamicSharedMemorySize, PH2_SMEM);

    // bf16 hi/lo splits + cell ring seed
    split_X_kernel<<<(M_TOTAL * IN_SZ + 255) / 256, 256>>>(X);
    split_W_kernel<<<(G4 * IN_SZ + 255) / 256, 256>>>(Wx);
    init_c_kernel<<<(B_SZ * H_SZ + 255) / 256, 256>>>(c0);

    // Phase 1: HMMA input projection (bf16x3 -> fp32).
    {
        dim3 g(G4 / 128, M_TOTAL / 128);    // (32, 256)
        gemm_x4_mma<<<g, 256, PH1_SMEM>>>(bias);
    }

    // Phase 2: persistent tensor-core recurrence.
    reset_bar_kernel<<<1, 1>>>();
    lstm_persistent<<<NBLK, 512, PH2_SMEM>>>(h0, Whr, mask, hiddens, h_last, c_last);
}

// round 12
// speedup vs baseline: 2.8864x; 1.0219x over previous
#include <cuda_runtime.h>
#include <cuda_bf16.h>
#include <math.h>
#include <stdint.h>

// Problem constants
#define T_STEPS 512
#define B_SZ    64
#define IN_SZ   1024
#define H_SZ    1024
#define G4      4096
#define M_TOTAL 32768          // T*B
#define NBLK    128            // persistent blocks (<=148 SMs -> all co-resident)

// ---------------------------------------------------------------------------
// Device scratch (no allocs allowed)
// ---------------------------------------------------------------------------
__device__ __align__(256) float         g_X4[(long long)M_TOTAL * G4];    // 512 MB
__device__ __align__(256) __nv_bfloat16 g_Xh[(long long)M_TOTAL * IN_SZ]; // 64 MB
__device__ __align__(256) __nv_bfloat16 g_Xl[(long long)M_TOTAL * IN_SZ]; // 64 MB
__device__ __align__(256) __nv_bfloat16 g_Wxh[(long long)G4 * IN_SZ];     // 8 MB
__device__ __align__(256) __nv_bfloat16 g_Wxl[(long long)G4 * IN_SZ];     // 8 MB
__device__ __align__(256) float         g_c2[2][B_SZ * H_SZ];             // fp32 cell ring
// Cell hi/lo rings in FRAGMENT-PERMUTED layout: within each 16-k group g,
// packed order is [2j, 2j+1, 8+2j, 9+2j] for j=0..3, so one 8-byte load per
// lane yields the (b0, b1) pair of an mma B fragment.
__device__ __align__(256) __nv_bfloat16 g_cph[2][B_SZ * H_SZ];
__device__ __align__(256) __nv_bfloat16 g_cpl[2][B_SZ * H_SZ];
__device__ int g_bar;

// perm(k): g = k>>4, r = k&15 -> g*16 + 4*((r&7)>>1) + 2*(r>>3) + (r&1)
// check: r=0->0 1->1 8->2 9->3 2->4 3->5 10->6 11->7 4->8 ... 15->15 (bijective)
__device__ __forceinline__ int perm_k(int k) {
    const int r = k & 15;
    return (k >> 4) * 16 + 4 * ((r & 7) >> 1) + 2 * (r >> 3) + (r & 1);
}

// ---------------------------------------------------------------------------
// Helpers (plain sm_103-safe PTX only: ldmatrix / mma.sync / cp.async)
// ---------------------------------------------------------------------------
__device__ __forceinline__ uint32_t smem_u32(const void* p) {
    uint32_t a;
    asm("{ .reg .u64 t; cvta.to.shared.u64 t, %1; cvt.u32.u64 %0, t; }" : "=r"(a) : "l"(p));
    return a;
}

__device__ __forceinline__ void cp16(uint32_t s, const void* g) {
    asm volatile("cp.async.cg.shared.global [%0], [%1], 16;" :: "r"(s), "l"(g));
}
#define CP_COMMIT() asm volatile("cp.async.commit_group;" ::: "memory")
#define CP_WAIT(n)  asm volatile("cp.async.wait_group %0;" :: "n"(n) : "memory")

__device__ __forceinline__ void ldsm_x4(uint32_t& r0, uint32_t& r1, uint32_t& r2,
                                        uint32_t& r3, uint32_t addr) {
    asm volatile("ldmatrix.sync.aligned.m8n8.x4.shared.b16 {%0,%1,%2,%3}, [%4];"
                 : "=r"(r0), "=r"(r1), "=r"(r2), "=r"(r3) : "r"(addr));
}

__device__ __forceinline__ void mma_bf16(float* c, const uint32_t* a, const uint32_t* b) {
    asm volatile(
        "mma.sync.aligned.m16n8k16.row.col.f32.bf16.bf16.f32 "
        "{%0,%1,%2,%3}, {%4,%5,%6,%7}, {%8,%9}, {%0,%1,%2,%3};"
        : "+f"(c[0]), "+f"(c[1]), "+f"(c[2]), "+f"(c[3])
        : "r"(a[0]), "r"(a[1]), "r"(a[2]), "r"(a[3]), "r"(b[0]), "r"(b[1]));
}

// ---------------------------------------------------------------------------
// bf16 hi/lo split kernels
// ---------------------------------------------------------------------------
__global__ void split_X_kernel(const float* __restrict__ src) {
    int i = blockIdx.x * blockDim.x + threadIdx.x;
    if (i < M_TOTAL * IN_SZ) {
        float x = src[i];
        __nv_bfloat16 h = __float2bfloat16(x);
        g_Xh[i] = h;
        g_Xl[i] = __float2bfloat16(x - __bfloat162float(h));
    }
}
__global__ void split_W_kernel(const float* __restrict__ src) {
    int i = blockIdx.x * blockDim.x + threadIdx.x;
    if (i < G4 * IN_SZ) {
        float x = src[i];
        __nv_bfloat16 h = __float2bfloat16(x);
        g_Wxh[i] = h;
        g_Wxl[i] = __float2bfloat16(x - __bfloat162float(h));
    }
}
// Seed cell ring slot 1 with c0 (fp32 + permuted hi/lo). Step t reads slot (t+1)&1.
__global__ void init_c_kernel(const float* __restrict__ c0) {
    int i = blockIdx.x * blockDim.x + threadIdx.x;
    if (i < B_SZ * H_SZ) {
        const int b = i >> 10, k = i & 1023;
        float x = c0[i];
        __nv_bfloat16 h = __float2bfloat16(x);
        g_c2[1][i] = x;
        const int kp = b * 1024 + perm_k(k);
        g_cph[1][kp] = h;
        g_cpl[1][kp] = __float2bfloat16(x - __bfloat162float(h));
    }
}

// ---------------------------------------------------------------------------
// Phase 1: X4 = X @ Wx^T + b via mma.sync bf16x3 (UNCHANGED from R11).
// ---------------------------------------------------------------------------
#define SPAD        40
#define TILE_ELEMS  (128 * SPAD)
#define TILE_BYTES  (TILE_ELEMS * 2)
#define STAGE_BYTES (4 * TILE_BYTES)
#define PH1_SMEM    (2 * STAGE_BYTES)

__device__ __forceinline__ void ph1_load_stage(
    uint32_t sbase, const __nv_bfloat16* Ah, const __nv_bfloat16* Al,
    const __nv_bfloat16* Bh, const __nv_bfloat16* Bl, int kt, int tid)
{
#pragma unroll
    for (int r = 0; r < 2; r++) {
        const int idx = tid + r * 256;
        const int row = idx >> 2;
        const int kq  = idx & 3;
        const uint32_t soff = (uint32_t)(row * SPAD + kq * 8) * 2;
        const long long goff = (long long)row * IN_SZ + kt + kq * 8;
        cp16(sbase + soff,                  Ah + goff);
        cp16(sbase + TILE_BYTES + soff,     Al + goff);
        cp16(sbase + 2 * TILE_BYTES + soff, Bh + goff);
        cp16(sbase + 3 * TILE_BYTES + soff, Bl + goff);
    }
}

__global__ __launch_bounds__(256, 1) void gemm_x4_mma(const float* __restrict__ bias) {
    extern __shared__ __align__(16) char smem[];
    const uint32_t sb = smem_u32(smem);

    const int tid  = threadIdx.x;
    const int wid  = tid >> 5;
    const int lane = tid & 31;
    const int n0 = blockIdx.x * 128;
    const int m0 = blockIdx.y * 128;

    const int wm = wid >> 1;
    const int wn = wid & 1;
    const int m_w = wm * 32;
    const int n_w = wn * 64;

    const int lrow = lane & 15;
    const int lk   = (lane >> 4) * 8;

    const __nv_bfloat16* Ah = g_Xh  + (long long)m0 * IN_SZ;
    const __nv_bfloat16* Al = g_Xl  + (long long)m0 * IN_SZ;
    const __nv_bfloat16* Bh = g_Wxh + (long long)n0 * IN_SZ;
    const __nv_bfloat16* Bl = g_Wxl + (long long)n0 * IN_SZ;

    float acc[2][8][4];
#pragma unroll
    for (int i = 0; i < 2; i++)
#pragma unroll
        for (int j = 0; j < 8; j++)
#pragma unroll
            for (int q = 0; q < 4; q++) acc[i][j][q] = 0.0f;

    ph1_load_stage(sb, Ah, Al, Bh, Bl, 0, tid);
    CP_COMMIT();

    for (int kt = 0; kt < 32; kt++) {
        if (kt + 1 < 32) {
            ph1_load_stage(sb + ((kt + 1) & 1) * STAGE_BYTES, Ah, Al, Bh, Bl,
                           (kt + 1) * 32, tid);
            CP_COMMIT();
            CP_WAIT(1);
        } else {
            CP_WAIT(0);
        }
        __syncthreads();

        const uint32_t st = sb + (kt & 1) * STAGE_BYTES;
#pragma unroll
        for (int ks = 0; ks < 32; ks += 16) {
            uint32_t ah[2][4], al[2][4];
#pragma unroll
            for (int tm = 0; tm < 2; tm++) {
                const uint32_t ao = (uint32_t)((m_w + tm * 16 + lrow) * SPAD + ks + lk) * 2;
                ldsm_x4(ah[tm][0], ah[tm][1], ah[tm][2], ah[tm][3], st + ao);
                ldsm_x4(al[tm][0], al[tm][1], al[tm][2], al[tm][3], st + TILE_BYTES + ao);
            }
            uint32_t bh[8][2], bl[8][2];
#pragma unroll
            for (int tn2 = 0; tn2 < 4; tn2++) {
                const uint32_t bo = (uint32_t)((n_w + tn2 * 16 + lrow) * SPAD + ks + lk) * 2;
                ldsm_x4(bh[tn2 * 2][0], bh[tn2 * 2 + 1][0], bh[tn2 * 2][1], bh[tn2 * 2 + 1][1],
                        st + 2 * TILE_BYTES + bo);
                ldsm_x4(bl[tn2 * 2][0], bl[tn2 * 2 + 1][0], bl[tn2 * 2][1], bl[tn2 * 2 + 1][1],
                        st + 3 * TILE_BYTES + bo);
            }
#pragma unroll
            for (int tm = 0; tm < 2; tm++)
#pragma unroll
                for (int tn = 0; tn < 8; tn++)
                    mma_bf16(acc[tm][tn], ah[tm], bh[tn]);
#pragma unroll
            for (int tm = 0; tm < 2; tm++)
#pragma unroll
                for (int tn = 0; tn < 8; tn++)
                    mma_bf16(acc[tm][tn], ah[tm], bl[tn]);
#pragma unroll
            for (int tm = 0; tm < 2; tm++)
#pragma unroll
                for (int tn = 0; tn < 8; tn++)
                    mma_bf16(acc[tm][tn], al[tm], bh[tn]);
        }
        __syncthreads();
    }

    const int gr = lane >> 2;
    const int gc = (lane & 3) * 2;
#pragma unroll
    for (int tm = 0; tm < 2; tm++) {
        const int row = m0 + m_w + tm * 16 + gr;
#pragma unroll
        for (int tn = 0; tn < 8; tn++) {
            const int col = n0 + n_w + tn * 8 + gc;
            const float2 bv = *(const float2*)(bias + col);
            float2 o0, o1;
            o0.x = acc[tm][tn][0] + bv.x; o0.y = acc[tm][tn][1] + bv.y;
            o1.x = acc[tm][tn][2] + bv.x; o1.y = acc[tm][tn][3] + bv.y;
            *(float2*)(g_X4 + (long long)row * G4 + col)       = o0;
            *(float2*)(g_X4 + (long long)(row + 8) * G4 + col) = o1;
        }
    }
}

// ---------------------------------------------------------------------------
// Phase 2: persistent tensor-core LSTM, operand-swapped.
// pre^T[32 gate-cols (m)][64 batch (n)] = WhSlice(A, smem ldsm) x c(B, direct LDG).
// 16 warps = 4 k-quarters x 4 batch-groups (16 rows). No staging, no mainloop
// syncthreads: c B-fragments load straight from L2 (permuted layout -> LDG.64),
// depth-2 software pipeline. One sync before the cross-quarter reduction.
//
// smem layout (bytes):
//   Ws hi : 0      .. 66048    col*2064 + k*2
//   Ws lo : 66048  .. 132096
//   P     : 132096 .. 166912   quarter*8704 + m*272 + n*4   ([4][32][68] f32)
//   X4s   : 166912 .. 176128   b*144 + col*4                ([64][36] f32)
//   mask  : 176128 .. 176384
// ---------------------------------------------------------------------------
#define SW_HL     66048
#define SW_ROW    2064
#define SP_OFF    132096
#define SP_ARR    8704
#define SX4_OFF   166912
#define SMASK_OFF 176128
#define PH2_SMEM  176384

__global__ void reset_bar_kernel() { g_bar = 0; }

__global__ __launch_bounds__(512, 1) void lstm_persistent(
    const float* __restrict__ h0,
    const float* __restrict__ Whr,     // [4096][1024]
    const int*   __restrict__ mask,    // [T][B]
    float* __restrict__ hiddens,       // [T][B][H]
    float* __restrict__ h_last, float* __restrict__ c_last)
{
    extern __shared__ __align__(16) char sm2[];
    const uint32_t sb = smem_u32(sm2);

    const int tid  = threadIdx.x;
    const int wid  = tid >> 5;
    const int lane = tid & 31;
    const int h0i  = blockIdx.x * 8;

    const int q  = wid >> 2;               // k-quarter (256 k)
    const int w  = wid & 3;                // batch group (16 rows)
    const int n0 = w * 16;
    const int lrow = lane & 15;
    const int lk   = (lane >> 4) * 8;
    const int gr   = lane >> 2;            // 0..7
    const int gcn  = (lane & 3) * 2;

    // Preload Wh slice as bf16 hi/lo: smem row lc -> Whr col (lc>>3)*H + h0i + (lc&7)
    for (int idx = tid; idx < 32 * 1024; idx += 512) {
        const int lc = idx >> 10;
        const int k  = idx & 1023;
        const int col = (lc >> 3) * H_SZ + h0i + (lc & 7);
        const float wv = Whr[(long long)col * H_SZ + k];
        const __nv_bfloat16 wh = __float2bfloat16(wv);
        *(__nv_bfloat16*)(sm2 + lc * SW_ROW + k * 2) = wh;
        *(__nv_bfloat16*)(sm2 + SW_HL + lc * SW_ROW + k * 2) =
            __float2bfloat16(wv - __bfloat162float(wh));
    }
    __syncthreads();

    // Epilogue constants: thread -> (batch eb, local h ej); permuted k index.
    const int eb = tid >> 3, ej = tid & 7;
    const int hg = h0i + ej;
    const int kp = perm_k(hg);

    for (int t = 0; t < T_STEPS; t++) {
        const int si = (t + 1) & 1;
        const int so = t & 1;
        const float* X4t = g_X4 + (long long)t * B_SZ * G4;

        // Arrive (finished step t-1; ordered by fence+sync at end of prev iter).
        if (t > 0 && tid == 0) atomicAdd(&g_bar, 1);

        // Prefetch X4 tile + mask into smem — independent of the barrier.
        {
            const int b = tid >> 3, seg = tid & 7;
            const int gate = seg >> 1, c4 = (seg & 1) * 4;
            cp16(sb + SX4_OFF + b * 144 + seg * 16,
                 X4t + (long long)b * G4 + gate * H_SZ + h0i + c4);
            if (tid < 16) cp16(sb + SMASK_OFF + tid * 16, mask + t * B_SZ + tid * 4);
        }
        CP_COMMIT();

        // Wait for all producers of the new c slot.
        if (t > 0) {
            if (tid == 0) {
                const int target = NBLK * t;
                while (*(volatile int*)&g_bar < target) { }
            }
            __syncthreads();
        }

        // Per-lane B bases: row = n0+gr (tile0) / +8 (tile1), lane byte (l&3)*8.
        const char* pbh = (const char*)(g_cph[si] + (long long)(n0 + gr) * H_SZ)
                        + (lane & 3) * 8;
        const char* pbl = (const char*)(g_cpl[si] + (long long)(n0 + gr) * H_SZ)
                        + (lane & 3) * 8;

        float acc[2][2][4];
#pragma unroll
        for (int i = 0; i < 2; i++)
#pragma unroll
            for (int j = 0; j < 2; j++)
#pragma unroll
                for (int r = 0; r < 4; r++) acc[i][j][r] = 0.0f;

        // Depth-2 pipelined B loads; k-step s offset = (q*16+s)*32 bytes.
        uint2 vbh[2][2], vbl[2][2];
        {
            const int off = q * 512;
            vbh[0][0] = __ldcg((const uint2*)(pbh + off));
            vbh[0][1] = __ldcg((const uint2*)(pbh + off + 8 * 2048));
            vbl[0][0] = __ldcg((const uint2*)(pbl + off));
            vbl[0][1] = __ldcg((const uint2*)(pbl + off + 8 * 2048));
        }

#pragma unroll
        for (int s = 0; s < 16; s++) {
            const int cur = s & 1;
            if (s + 1 < 16) {
                const int off = (q * 16 + s + 1) * 32;
                vbh[cur ^ 1][0] = __ldcg((const uint2*)(pbh + off));
                vbh[cur ^ 1][1] = __ldcg((const uint2*)(pbh + off + 8 * 2048));
                vbl[cur ^ 1][0] = __ldcg((const uint2*)(pbl + off));
                vbl[cur ^ 1][1] = __ldcg((const uint2*)(pbl + off + 8 * 2048));
            }
            const int k0 = q * 256 + s * 16;
            uint32_t ah[2][4], al[2][4];
#pragma unroll
            for (int mt = 0; mt < 2; mt++) {
                const uint32_t ao = sb + (uint32_t)(mt * 16 + lrow) * SW_ROW + (k0 + lk) * 2;
                ldsm_x4(ah[mt][0], ah[mt][1], ah[mt][2], ah[mt][3], ao);
                ldsm_x4(al[mt][0], al[mt][1], al[mt][2], al[mt][3], ao + SW_HL);
            }
            uint32_t bhf[2][2] = {{vbh[cur][0].x, vbh[cur][0].y},
                                  {vbh[cur][1].x, vbh[cur][1].y}};
            uint32_t blf[2][2] = {{vbl[cur][0].x, vbl[cur][0].y},
                                  {vbl[cur][1].x, vbl[cur][1].y}};
            // Term-outer: 4 independent MMAs between accumulator reuse.
#pragma unroll
            for (int mt = 0; mt < 2; mt++)
#pragma unroll
                for (int nt = 0; nt < 2; nt++) mma_bf16(acc[mt][nt], ah[mt], bhf[nt]);
#pragma unroll
            for (int mt = 0; mt < 2; mt++)
#pragma unroll
                for (int nt = 0; nt < 2; nt++) mma_bf16(acc[mt][nt], ah[mt], blf[nt]);
#pragma unroll
            for (int mt = 0; mt < 2; mt++)
#pragma unroll
                for (int nt = 0; nt < 2; nt++) mma_bf16(acc[mt][nt], al[mt], bhf[nt]);
        }

        CP_WAIT(0);   // X4/mask prefetch done (this thread's groups)

        // Write per-quarter partials: P[q][m=gate-col][n=batch].
        {
            float* Pq = (float*)(sm2 + SP_OFF + q * SP_ARR);
#pragma unroll
            for (int mt = 0; mt < 2; mt++)
#pragma unroll
                for (int nt = 0; nt < 2; nt++) {
                    const int m = mt * 16 + gr;
                    const int n = n0 + nt * 8 + gcn;
                    float2 v0 = {acc[mt][nt][0], acc[mt][nt][1]};
                    float2 v1 = {acc[mt][nt][2], acc[mt][nt][3]};
                    *(float2*)&Pq[m * 68 + n]       = v0;
                    *(float2*)&Pq[(m + 8) * 68 + n] = v1;
                }
        }
        __syncthreads();

        // Epilogue: 512 threads, one (b, h) pair each.
        {
            const float* X4s = (const float*)(sm2 + SX4_OFF);
            float pre[4];
#pragma unroll
            for (int g = 0; g < 4; g++) {
                const int lc = g * 8 + ej;
                float v = X4s[eb * 36 + lc];
#pragma unroll
                for (int qq = 0; qq < 4; qq++)
                    v += ((const float*)(sm2 + SP_OFF + qq * SP_ARR))[lc * 68 + eb];
                pre[g] = v;
            }

            const float ig = 1.0f / (1.0f + expf(-pre[0]));
            const float fg = 1.0f / (1.0f + expf(-pre[1]));
            const float og = 1.0f / (1.0f + expf(-pre[2]));

            const float cp = __ldcg(g_c2[si] + eb * H_SZ + hg);
            float c = fg * cp + ig * tanhf(pre[3]);
            float h = og * tanhf(c);
            if (((const int*)(sm2 + SMASK_OFF))[eb] == 0) {
                h = (t == 0) ? h0[eb * H_SZ + hg]
                             : __ldcg(hiddens + (long long)(t - 1) * B_SZ * H_SZ + eb * H_SZ + hg);
                c = cp;
            }
            hiddens[(long long)t * B_SZ * H_SZ + eb * H_SZ + hg] = h;
            g_c2[so][eb * H_SZ + hg] = c;
            const __nv_bfloat16 chv = __float2bfloat16(c);
            g_cph[so][eb * H_SZ + kp] = chv;
            g_cpl[so][eb * H_SZ + kp] = __float2bfloat16(c - __bfloat162float(chv));
            if (t == T_STEPS - 1) {
                h_last[eb * H_SZ + hg] = h;
                c_last[eb * H_SZ + hg] = c;
            }
        }

        // Order c writes before the next step's arrive.
        if (t < T_STEPS - 1) {
            __threadfence();
            __syncthreads();
        }
    }
}

// ---------------------------------------------------------------------------
// Launch. Inputs (metadata order):
// 0: X [T,B,IN] f32  1: h0 [B,H] f32  2: c0 [B,H] f32  3: mask [T,B] i32
// 4: W_x_ifoc [4H,IN] f32  5: W_h_ifoc [4H,H] f32  6: b_ifoc [4H] f32
// d_out: [hiddens (T*B*H) | h_last (B*H) | c_last (B*H)] f32
// ---------------------------------------------------------------------------
extern "C" void kernel_launch(void* const* d_in, const int* in_sizes, int n_in,
                              void* d_out, int out_size)
{
    const float* X    = (const float*)d_in[0];
    const float* h0   = (const float*)d_in[1];
    const float* c0   = (const float*)d_in[2];
    const int*   mask = (const int*)d_in[3];
    const float* Wx   = (const float*)d_in[4];
    const float* Whr  = (const float*)d_in[5];
    const float* bias = (const float*)d_in[6];

    float* out     = (float*)d_out;
    float* hiddens = out;
    float* h_last  = out + (long long)T_STEPS * B_SZ * H_SZ;
    float* c_last  = h_last + B_SZ * H_SZ;

    cudaFuncSetAttribute(gemm_x4_mma, cudaFuncAttributeMaxDynamicSharedMemorySize, PH1_SMEM);
    cudaFuncSetAttribute(lstm_persistent, cudaFuncAttributeMaxDynamicSharedMemorySize, PH2_SMEM);

    // bf16 hi/lo splits + cell ring seed
    split_X_kernel<<<(M_TOTAL * IN_SZ + 255) / 256, 256>>>(X);
    split_W_kernel<<<(G4 * IN_SZ + 255) / 256, 256>>>(Wx);
    init_c_kernel<<<(B_SZ * H_SZ + 255) / 256, 256>>>(c0);

    // Phase 1: HMMA input projection (bf16x3 -> fp32).
    {
        dim3 g(G4 / 128, M_TOTAL / 128);    // (32, 256)
        gemm_x4_mma<<<g, 256, PH1_SMEM>>>(bias);
    }

    // Phase 2: persistent tensor-core recurrence (operand-swapped, no staging).
    reset_bar_kernel<<<1, 1>>>();
    lstm_persistent<<<NBLK, 512, PH2_SMEM>>>(h0, Whr, mask, hiddens, h_last, c_last);
}